// round 1
// baseline (speedup 1.0000x reference)
#include <cuda_runtime.h>
#include <math.h>
#include <stdint.h>

// ---------------- problem constants (fixed by setup_inputs) ----------------
#define BFRAMES   128          // B*T = 8*16
#define SEQ       256          // H*W = 16*16
#define DMODEL    1152
#define NHEADS    12
#define NGROUPS   4
#define HEADDIM   96
#define QKV_N     1920         // 12*96 + 2*4*96
#define MTOK      32768        // BFRAMES*SEQ
#define AXISD     32
#define SM_SCALE  0.1020620726159658f   // 96^-0.5

// ---------------- scratch (device globals; no allocation allowed) ----------
__device__ float g_qkv[(size_t)MTOK * QKV_N];                    // 251.7 MB
__device__ float g_q[(size_t)BFRAMES * NHEADS * SEQ * HEADDIM];  // 113 MB
__device__ float g_k[(size_t)BFRAMES * NGROUPS * SEQ * HEADDIM]; // 37.7 MB
__device__ float g_v[(size_t)BFRAMES * NGROUPS * SEQ * HEADDIM]; // 37.7 MB
__device__ float g_o[(size_t)MTOK * DMODEL];                     // 151 MB

// ============================================================================
// SGEMM (NT): C[M,N] = A[M,K] * B[N,K]^T.  128x128 block, BK=16, 8x8 microtile.
// M,N multiples of 128; K multiple of 16 (holds for all our calls).
// ============================================================================
__global__ __launch_bounds__(256) void sgemm_nt(
    const float* __restrict__ A, const float* __restrict__ B,
    float* __restrict__ C, int M, int N, int K)
{
    __shared__ float As[16 * 128];
    __shared__ float Bs[16 * 128];

    const int tid = threadIdx.x;
    const int ty  = tid >> 4;         // 0..15
    const int tx  = tid & 15;         // 0..15
    const int rowBase = blockIdx.y * 128;
    const int colBase = blockIdx.x * 128;

    const float* Aptr = A + (size_t)rowBase * K;
    const float* Bptr = B + (size_t)colBase * K;

    const int lrow = tid >> 2;        // 0..63
    const int lkv  = (tid & 3) * 4;   // 0,4,8,12

    float acc[8][8];
#pragma unroll
    for (int i = 0; i < 8; i++)
#pragma unroll
        for (int j = 0; j < 8; j++) acc[i][j] = 0.f;

    for (int k0 = 0; k0 < K; k0 += 16) {
#pragma unroll
        for (int half = 0; half < 2; half++) {
            int r = lrow + half * 64;
            float4 a = *(const float4*)(Aptr + (size_t)r * K + k0 + lkv);
            As[(lkv + 0) * 128 + r] = a.x;
            As[(lkv + 1) * 128 + r] = a.y;
            As[(lkv + 2) * 128 + r] = a.z;
            As[(lkv + 3) * 128 + r] = a.w;
            float4 b = *(const float4*)(Bptr + (size_t)r * K + k0 + lkv);
            Bs[(lkv + 0) * 128 + r] = b.x;
            Bs[(lkv + 1) * 128 + r] = b.y;
            Bs[(lkv + 2) * 128 + r] = b.z;
            Bs[(lkv + 3) * 128 + r] = b.w;
        }
        __syncthreads();

#pragma unroll
        for (int kk = 0; kk < 16; kk++) {
            float ra[8], rb[8];
            float4 a0 = *(const float4*)&As[kk * 128 + ty * 8 + 0];
            float4 a1 = *(const float4*)&As[kk * 128 + ty * 8 + 4];
            float4 b0 = *(const float4*)&Bs[kk * 128 + tx * 8 + 0];
            float4 b1 = *(const float4*)&Bs[kk * 128 + tx * 8 + 4];
            ra[0]=a0.x; ra[1]=a0.y; ra[2]=a0.z; ra[3]=a0.w;
            ra[4]=a1.x; ra[5]=a1.y; ra[6]=a1.z; ra[7]=a1.w;
            rb[0]=b0.x; rb[1]=b0.y; rb[2]=b0.z; rb[3]=b0.w;
            rb[4]=b1.x; rb[5]=b1.y; rb[6]=b1.z; rb[7]=b1.w;
#pragma unroll
            for (int i = 0; i < 8; i++)
#pragma unroll
                for (int j = 0; j < 8; j++)
                    acc[i][j] = fmaf(ra[i], rb[j], acc[i][j]);
        }
        __syncthreads();
    }

#pragma unroll
    for (int i = 0; i < 8; i++) {
        size_t crow = (size_t)(rowBase + ty * 8 + i) * N + colBase + tx * 8;
        float4 v0 = make_float4(acc[i][0], acc[i][1], acc[i][2], acc[i][3]);
        float4 v1 = make_float4(acc[i][4], acc[i][5], acc[i][6], acc[i][7]);
        *(float4*)(C + crow + 0) = v0;
        *(float4*)(C + crow + 4) = v1;
    }
}

// ============================================================================
// norm + RoPE + layout transpose. One warp per 96-dim head vector.
//   q: norm + rope -> g_q [bf,h,s,d]
//   k: norm + rope -> g_k [bf,g,s,d]
//   v: copy        -> g_v [bf,g,s,d]
// RoPE: pos = (s/16 + s%16); inv_freq[i] = 10000^(-i/16), i<16;
//   out[d<16]      = x[2d]*cos   - x[2d+1]*sin
//   out[16<=d<32]  = x[2(d-16)]*sin + x[2(d-16)+1]*cos
// ============================================================================
__global__ __launch_bounds__(256) void normrope_kernel(const float* __restrict__ qkv)
{
    const int NQv = MTOK * NHEADS;   // 393216
    const int NKv = MTOK * NGROUPS;  // 131072
    int wid  = (blockIdx.x * blockDim.x + threadIdx.x) >> 5;
    int lane = threadIdx.x & 31;
    if (wid >= NQv + 2 * NKv) return;

    const float* src;
    float* dst;
    int t;
    bool do_norm_rope = true;

    if (wid < NQv) {
        t = wid / NHEADS; int h = wid % NHEADS;
        src = qkv + (size_t)t * QKV_N + h * HEADDIM;
        int bf = t >> 8, s = t & 255;
        dst = g_q + ((size_t)(bf * NHEADS + h) * SEQ + s) * HEADDIM;
    } else if (wid < NQv + NKv) {
        int v = wid - NQv; t = v / NGROUPS; int g = v % NGROUPS;
        src = qkv + (size_t)t * QKV_N + DMODEL + g * HEADDIM;
        int bf = t >> 8, s = t & 255;
        dst = g_k + ((size_t)(bf * NGROUPS + g) * SEQ + s) * HEADDIM;
    } else {
        int v = wid - NQv - NKv; t = v / NGROUPS; int g = v % NGROUPS;
        src = qkv + (size_t)t * QKV_N + DMODEL + NGROUPS * HEADDIM + g * HEADDIM;
        int bf = t >> 8, s = t & 255;
        dst = g_v + ((size_t)(bf * NGROUPS + g) * SEQ + s) * HEADDIM;
        do_norm_rope = false;
    }

    float x0 = src[lane], x1 = src[lane + 32], x2 = src[lane + 64];

    if (do_norm_rope) {
        float ss = fmaf(x0, x0, fmaf(x1, x1, x2 * x2));
#pragma unroll
        for (int o = 16; o; o >>= 1) ss += __shfl_xor_sync(0xffffffffu, ss, o);
        float inv = 1.0f / fmaxf(sqrtf(ss), 1e-10f);
        x0 *= inv; x1 *= inv; x2 *= inv;

        int s = t & 255;
        float pos = (float)((s >> 4) + (s & 15));
        int i = lane & 15;
        float a = __shfl_sync(0xffffffffu, x0, 2 * i);
        float b = __shfl_sync(0xffffffffu, x0, 2 * i + 1);
        // inv_freq = exp2(-i/16 * log2(10000)); log2(10000)=13.287712379549449
        float invf = exp2f(-(float)i * 0.8304820237218406f);
        float ang = pos * invf;
        float sn, cs;
        sincosf(ang, &sn, &cs);
        x0 = (lane < 16) ? fmaf(a, cs, -b * sn) : fmaf(a, sn, b * cs);
    }

    dst[lane]      = x0;
    dst[lane + 32] = x1;
    dst[lane + 64] = x2;
}

// ============================================================================
// Attention. Block = (bf, head, 32-query chunk), 256 threads.
// Two-pass softmax with scores tile in shared. Writes g_o in [token, h*96+d].
// ============================================================================
#define QSTRIDE 97
#define ATTN_SMEM_FLOATS (32*QSTRIDE + 64*QSTRIDE + 32*256 + 32)
#define ATTN_SMEM_BYTES  (ATTN_SMEM_FLOATS * 4)

__global__ __launch_bounds__(256) void attn_kernel()
{
    extern __shared__ float sm[];
    float* q_s   = sm;                      // [32][97]
    float* kv_s  = sm + 32 * QSTRIDE;       // [64][97]
    float* sc    = kv_s + 64 * QSTRIDE;     // [32][256]
    float* row_l = sc + 32 * 256;           // [32]

    const int tid = threadIdx.x;
    const int qc = blockIdx.x;   // 0..7
    const int h  = blockIdx.y;   // 0..11
    const int bf = blockIdx.z;   // 0..127
    const int g  = h / 3;        // HEADS_PER_GROUP = 3

    const float* qb = g_q + ((size_t)(bf * NHEADS + h) * SEQ + qc * 32) * HEADDIM;
    const float* kb = g_k + (size_t)(bf * NGROUPS + g) * SEQ * HEADDIM;
    const float* vb = g_v + (size_t)(bf * NGROUPS + g) * SEQ * HEADDIM;

    for (int idx = tid; idx < 32 * HEADDIM; idx += 256) {
        int r = idx / HEADDIM, d = idx % HEADDIM;
        q_s[r * QSTRIDE + d] = qb[r * HEADDIM + d];
    }

    // ---- scores ----
    const int srow = tid >> 3;       // 0..31
    const int scb  = tid & 7;        // 0..7
    for (int kt = 0; kt < 4; kt++) {
        __syncthreads();
        for (int idx = tid; idx < 64 * HEADDIM; idx += 256) {
            int r = idx / HEADDIM, d = idx % HEADDIM;
            kv_s[r * QSTRIDE + d] = kb[(size_t)(kt * 64 + r) * HEADDIM + d];
        }
        __syncthreads();
        float acc[8];
#pragma unroll
        for (int j = 0; j < 8; j++) acc[j] = 0.f;
        for (int d = 0; d < HEADDIM; d++) {
            float qv = q_s[srow * QSTRIDE + d];
#pragma unroll
            for (int j = 0; j < 8; j++)
                acc[j] = fmaf(qv, kv_s[(scb + j * 8) * QSTRIDE + d], acc[j]);
        }
#pragma unroll
        for (int j = 0; j < 8; j++)
            sc[srow * 256 + kt * 64 + scb + j * 8] = acc[j] * SM_SCALE;
    }
    __syncthreads();

    // ---- softmax (warp per 4 rows) ----
    const int warp = tid >> 5, lane = tid & 31;
    for (int r = warp * 4; r < warp * 4 + 4; r++) {
        float m = -INFINITY;
        for (int c = lane; c < 256; c += 32) m = fmaxf(m, sc[r * 256 + c]);
#pragma unroll
        for (int o = 16; o; o >>= 1) m = fmaxf(m, __shfl_xor_sync(0xffffffffu, m, o));
        float l = 0.f;
        for (int c = lane; c < 256; c += 32) {
            float e = expf(sc[r * 256 + c] - m);
            sc[r * 256 + c] = e;
            l += e;
        }
#pragma unroll
        for (int o = 16; o; o >>= 1) l += __shfl_xor_sync(0xffffffffu, l, o);
        if (lane == 0) row_l[r] = l;
    }
    __syncthreads();

    // ---- output: O = P @ V ----
    const int orow = tid >> 3;           // 0..31
    const int odb  = (tid & 7) * 12;     // 0..84 step 12
    float oacc[12];
#pragma unroll
    for (int j = 0; j < 12; j++) oacc[j] = 0.f;

    for (int kt = 0; kt < 4; kt++) {
        __syncthreads();
        for (int idx = tid; idx < 64 * HEADDIM; idx += 256) {
            int r = idx / HEADDIM, d = idx % HEADDIM;
            kv_s[r * QSTRIDE + d] = vb[(size_t)(kt * 64 + r) * HEADDIM + d];
        }
        __syncthreads();
        for (int c = 0; c < 64; c++) {
            float p = sc[orow * 256 + kt * 64 + c];
#pragma unroll
            for (int j = 0; j < 12; j++)
                oacc[j] = fmaf(p, kv_s[c * QSTRIDE + odb + j], oacc[j]);
        }
    }

    float invl = 1.0f / row_l[orow];
    size_t obase = (size_t)(bf * SEQ + qc * 32 + orow) * DMODEL + h * HEADDIM + odb;
#pragma unroll
    for (int j = 0; j < 12; j++)
        g_o[obase + j] = oacc[j] * invl;
}

// ============================================================================
// launch
// ============================================================================
extern "C" void kernel_launch(void* const* d_in, const int* in_sizes, int n_in,
                              void* d_out, int out_size)
{
    const float* x     = (const float*)d_in[0];
    const float* w_qkv = (const float*)d_in[1];
    const float* w_o   = (const float*)d_in[2];
    float* out = (float*)d_out;

    float *qkv_p, *o_p;
    cudaGetSymbolAddress((void**)&qkv_p, g_qkv);
    cudaGetSymbolAddress((void**)&o_p, g_o);

    cudaFuncSetAttribute(attn_kernel,
                         cudaFuncAttributeMaxDynamicSharedMemorySize,
                         ATTN_SMEM_BYTES);

    // 1) QKV projection: [32768,1920] = x[32768,1152] @ w_qkv^T
    sgemm_nt<<<dim3(QKV_N / 128, MTOK / 128), 256>>>(x, w_qkv, qkv_p, MTOK, QKV_N, DMODEL);

    // 2) qk-norm + spatial RoPE + layout transpose
    {
        int total_warps = MTOK * NHEADS + 2 * MTOK * NGROUPS;  // 655360
        normrope_kernel<<<total_warps / 8, 256>>>(qkv_p);
    }

    // 3) attention
    attn_kernel<<<dim3(8, NHEADS, BFRAMES), 256, ATTN_SMEM_BYTES>>>();

    // 4) output projection: out[32768,1152] = o @ w_o^T
    sgemm_nt<<<dim3(DMODEL / 128, MTOK / 128), 256>>>(o_p, w_o, out, MTOK, DMODEL, DMODEL);
}

// round 3
// speedup vs baseline: 1.9119x; 1.9119x over previous
#include <cuda_runtime.h>
#include <math.h>
#include <stdint.h>

// ---------------- problem constants (fixed by setup_inputs) ----------------
#define BFRAMES   128          // B*T = 8*16
#define SEQ       256          // H*W = 16*16
#define DMODEL    1152
#define NHEADS    12
#define NGROUPS   4
#define HEADDIM   96
#define QKV_N     1920         // 12*96 + 2*4*96
#define MTOK      32768        // BFRAMES*SEQ
#define SM_SCALE  0.1020620726159658f   // 96^-0.5

// ---------------- scratch (device globals; no allocation allowed) ----------
__device__ float g_qkv[(size_t)MTOK * QKV_N];
__device__ float g_q[(size_t)BFRAMES * NHEADS * SEQ * HEADDIM];
__device__ float g_k[(size_t)BFRAMES * NGROUPS * SEQ * HEADDIM];
__device__ float g_v[(size_t)BFRAMES * NGROUPS * SEQ * HEADDIM];
__device__ float g_o[(size_t)MTOK * DMODEL];          // rounded x, then attn output
__device__ float g_wr[(size_t)QKV_N * DMODEL];        // rounded weights

// ============================================================================
// helpers
// ============================================================================
__device__ __forceinline__ uint32_t smem_u32(const void* p) {
    uint32_t a;
    asm("{ .reg .u64 t; cvta.to.shared.u64 t, %1; cvt.u32.u64 %0, t; }"
        : "=r"(a) : "l"(p));
    return a;
}

__device__ __forceinline__ void cp_async16(uint32_t saddr, const void* gptr) {
    asm volatile("cp.async.cg.shared.global [%0], [%1], 16;" :: "r"(saddr), "l"(gptr));
}

__device__ __forceinline__ void mma_tf32(float c[4], uint32_t a0, uint32_t a1,
                                         uint32_t a2, uint32_t a3,
                                         uint32_t b0, uint32_t b1) {
    asm volatile(
        "mma.sync.aligned.m16n8k8.row.col.f32.tf32.tf32.f32 "
        "{%0,%1,%2,%3}, {%4,%5,%6,%7}, {%8,%9}, {%0,%1,%2,%3};"
        : "+f"(c[0]), "+f"(c[1]), "+f"(c[2]), "+f"(c[3])
        : "r"(a0), "r"(a1), "r"(a2), "r"(a3), "r"(b0), "r"(b1));
}

// ============================================================================
// tf32 mma.sync GEMM (NT): C[M,N] = A[M,K] * B[N,K]^T, both row-major (K-major).
// CTA tile 256x128, BK=32, 3-stage cp.async pipeline, 8 warps (warp tile 64x64).
// A,B must be pre-rounded to tf32 values.
// Smem per stage: A 256x36 floats (36864B) + B 128x36 floats (18432B) = 55296B.
// ============================================================================
#define GPAD        36
#define STAGE_F     (256 * GPAD + 128 * GPAD)   // 13824 floats
#define GEMM_SMEM   (3 * STAGE_F * 4)           // 165888 bytes

__global__ __launch_bounds__(256, 1)
void gemm_tf32(const float* __restrict__ A, const float* __restrict__ B,
               float* __restrict__ C, int ldC, int K)
{
    extern __shared__ float smf[];
    const int tid    = threadIdx.x;
    const int lane   = tid & 31;
    const int wid    = tid >> 5;
    const int warp_m = wid & 3;     // 4 warps over M (64 each)
    const int warp_n = wid >> 2;    // 2 warps over N (64 each)
    const int m0 = blockIdx.y * 256;
    const int n0 = blockIdx.x * 128;
    const int ITERS = K >> 5;

    const float* Ag = A + (size_t)m0 * K;
    const float* Bg = B + (size_t)n0 * K;
    const uint32_t sbase = smem_u32(smf);

    // ---- async stage loader ----
    auto load_stage = [&](int chunk, int st) {
        uint32_t abase = sbase + st * (STAGE_F * 4);
        uint32_t bbase = abase + 256 * GPAD * 4;
        const float* Ac = Ag + chunk * 32;
        const float* Bc = Bg + chunk * 32;
#pragma unroll
        for (int j = 0; j < 8; j++) {            // A: 256 rows x 8 chunks of 16B
            int idx = tid + j * 256;
            int row = idx >> 3, c = idx & 7;
            cp_async16(abase + row * (GPAD * 4) + c * 16,
                       Ac + (size_t)row * K + c * 4);
        }
#pragma unroll
        for (int j = 0; j < 4; j++) {            // B: 128 rows x 8 chunks of 16B
            int idx = tid + j * 256;
            int row = idx >> 3, c = idx & 7;
            cp_async16(bbase + row * (GPAD * 4) + c * 16,
                       Bc + (size_t)row * K + c * 4);
        }
    };

    float acc[4][8][4];
#pragma unroll
    for (int mt = 0; mt < 4; mt++)
#pragma unroll
        for (int nt = 0; nt < 8; nt++)
#pragma unroll
            for (int r = 0; r < 4; r++) acc[mt][nt][r] = 0.f;

    load_stage(0, 0);
    asm volatile("cp.async.commit_group;");
    if (ITERS > 1) load_stage(1, 1);
    asm volatile("cp.async.commit_group;");

    for (int i = 0; i < ITERS; i++) {
        const int st = i % 3;
        asm volatile("cp.async.wait_group 1;");
        __syncthreads();

        if (i + 2 < ITERS) load_stage(i + 2, (i + 2) % 3);
        asm volatile("cp.async.commit_group;");

        // fragment base pointers for this stage
        const float* Ab = smf + st * STAGE_F
                        + (warp_m * 64 + (lane >> 2)) * GPAD + (lane & 3);
        const float* Bb = smf + st * STAGE_F + 256 * GPAD
                        + (warp_n * 64 + (lane >> 2)) * GPAD + (lane & 3);

#pragma unroll
        for (int ks = 0; ks < 4; ks++) {
            const int k0 = ks * 8;
            uint32_t af[4][4];
#pragma unroll
            for (int mt = 0; mt < 4; mt++) {
                af[mt][0] = __float_as_uint(Ab[mt * 16 * GPAD + k0]);
                af[mt][1] = __float_as_uint(Ab[mt * 16 * GPAD + 8 * GPAD + k0]);
                af[mt][2] = __float_as_uint(Ab[mt * 16 * GPAD + k0 + 4]);
                af[mt][3] = __float_as_uint(Ab[mt * 16 * GPAD + 8 * GPAD + k0 + 4]);
            }
            uint32_t bf[8][2];
#pragma unroll
            for (int nt = 0; nt < 8; nt++) {
                bf[nt][0] = __float_as_uint(Bb[nt * 8 * GPAD + k0]);
                bf[nt][1] = __float_as_uint(Bb[nt * 8 * GPAD + k0 + 4]);
            }
#pragma unroll
            for (int mt = 0; mt < 4; mt++)
#pragma unroll
                for (int nt = 0; nt < 8; nt++)
                    mma_tf32(acc[mt][nt], af[mt][0], af[mt][1], af[mt][2], af[mt][3],
                             bf[nt][0], bf[nt][1]);
        }
        __syncthreads();
    }

    // ---- epilogue ----
#pragma unroll
    for (int mt = 0; mt < 4; mt++) {
        int row0 = m0 + warp_m * 64 + mt * 16 + (lane >> 2);
#pragma unroll
        for (int nt = 0; nt < 8; nt++) {
            int col = n0 + warp_n * 64 + nt * 8 + (lane & 3) * 2;
            float2 v0 = make_float2(acc[mt][nt][0], acc[mt][nt][1]);
            float2 v1 = make_float2(acc[mt][nt][2], acc[mt][nt][3]);
            *(float2*)(C + (size_t)row0 * ldC + col) = v0;
            *(float2*)(C + (size_t)(row0 + 8) * ldC + col) = v1;
        }
    }
}

// ============================================================================
// round fp32 -> tf32 (RNA) elementwise, vectorized
// ============================================================================
__global__ __launch_bounds__(256) void round_tf32_kernel(
    const float4* __restrict__ in, float4* __restrict__ out, int n4)
{
    int i = blockIdx.x * blockDim.x + threadIdx.x;
    if (i >= n4) return;
    float4 v = in[i];
    uint32_t a, b, c, d;
    asm("cvt.rna.tf32.f32 %0, %1;" : "=r"(a) : "f"(v.x));
    asm("cvt.rna.tf32.f32 %0, %1;" : "=r"(b) : "f"(v.y));
    asm("cvt.rna.tf32.f32 %0, %1;" : "=r"(c) : "f"(v.z));
    asm("cvt.rna.tf32.f32 %0, %1;" : "=r"(d) : "f"(v.w));
    out[i] = make_float4(__uint_as_float(a), __uint_as_float(b),
                         __uint_as_float(c), __uint_as_float(d));
}

// ============================================================================
// norm + RoPE + layout transpose (unchanged, R1-proven)
// ============================================================================
__global__ __launch_bounds__(256) void normrope_kernel(const float* __restrict__ qkv)
{
    const int NQv = MTOK * NHEADS;
    const int NKv = MTOK * NGROUPS;
    int wid  = (blockIdx.x * blockDim.x + threadIdx.x) >> 5;
    int lane = threadIdx.x & 31;
    if (wid >= NQv + 2 * NKv) return;

    const float* src;
    float* dst;
    int t;
    bool do_norm_rope = true;

    if (wid < NQv) {
        t = wid / NHEADS; int h = wid % NHEADS;
        src = qkv + (size_t)t * QKV_N + h * HEADDIM;
        int bf = t >> 8, s = t & 255;
        dst = g_q + ((size_t)(bf * NHEADS + h) * SEQ + s) * HEADDIM;
    } else if (wid < NQv + NKv) {
        int v = wid - NQv; t = v / NGROUPS; int g = v % NGROUPS;
        src = qkv + (size_t)t * QKV_N + DMODEL + g * HEADDIM;
        int bf = t >> 8, s = t & 255;
        dst = g_k + ((size_t)(bf * NGROUPS + g) * SEQ + s) * HEADDIM;
    } else {
        int v = wid - NQv - NKv; t = v / NGROUPS; int g = v % NGROUPS;
        src = qkv + (size_t)t * QKV_N + DMODEL + NGROUPS * HEADDIM + g * HEADDIM;
        int bf = t >> 8, s = t & 255;
        dst = g_v + ((size_t)(bf * NGROUPS + g) * SEQ + s) * HEADDIM;
        do_norm_rope = false;
    }

    float x0 = src[lane], x1 = src[lane + 32], x2 = src[lane + 64];

    if (do_norm_rope) {
        float ss = fmaf(x0, x0, fmaf(x1, x1, x2 * x2));
#pragma unroll
        for (int o = 16; o; o >>= 1) ss += __shfl_xor_sync(0xffffffffu, ss, o);
        float inv = 1.0f / fmaxf(sqrtf(ss), 1e-10f);
        x0 *= inv; x1 *= inv; x2 *= inv;

        int s = t & 255;
        float pos = (float)((s >> 4) + (s & 15));
        int i = lane & 15;
        float a = __shfl_sync(0xffffffffu, x0, 2 * i);
        float b = __shfl_sync(0xffffffffu, x0, 2 * i + 1);
        float invf = exp2f(-(float)i * 0.8304820237218406f);
        float ang = pos * invf;
        float sn, cs;
        sincosf(ang, &sn, &cs);
        x0 = (lane < 16) ? fmaf(a, cs, -b * sn) : fmaf(a, sn, b * cs);
    }

    dst[lane]      = x0;
    dst[lane + 32] = x1;
    dst[lane + 64] = x2;
}

// ============================================================================
// Attention (unchanged, R1-proven)
// ============================================================================
#define QSTRIDE 97
#define ATTN_SMEM_FLOATS (32*QSTRIDE + 64*QSTRIDE + 32*256 + 32)
#define ATTN_SMEM_BYTES  (ATTN_SMEM_FLOATS * 4)

__global__ __launch_bounds__(256) void attn_kernel()
{
    extern __shared__ float sm[];
    float* q_s   = sm;
    float* kv_s  = sm + 32 * QSTRIDE;
    float* sc    = kv_s + 64 * QSTRIDE;
    float* row_l = sc + 32 * 256;

    const int tid = threadIdx.x;
    const int qc = blockIdx.x;
    const int h  = blockIdx.y;
    const int bf = blockIdx.z;
    const int g  = h / 3;

    const float* qb = g_q + ((size_t)(bf * NHEADS + h) * SEQ + qc * 32) * HEADDIM;
    const float* kb = g_k + (size_t)(bf * NGROUPS + g) * SEQ * HEADDIM;
    const float* vb = g_v + (size_t)(bf * NGROUPS + g) * SEQ * HEADDIM;

    for (int idx = tid; idx < 32 * HEADDIM; idx += 256) {
        int r = idx / HEADDIM, d = idx % HEADDIM;
        q_s[r * QSTRIDE + d] = qb[r * HEADDIM + d];
    }

    const int srow = tid >> 3;
    const int scb  = tid & 7;
    for (int kt = 0; kt < 4; kt++) {
        __syncthreads();
        for (int idx = tid; idx < 64 * HEADDIM; idx += 256) {
            int r = idx / HEADDIM, d = idx % HEADDIM;
            kv_s[r * QSTRIDE + d] = kb[(size_t)(kt * 64 + r) * HEADDIM + d];
        }
        __syncthreads();
        float acc[8];
#pragma unroll
        for (int j = 0; j < 8; j++) acc[j] = 0.f;
        for (int d = 0; d < HEADDIM; d++) {
            float qv = q_s[srow * QSTRIDE + d];
#pragma unroll
            for (int j = 0; j < 8; j++)
                acc[j] = fmaf(qv, kv_s[(scb + j * 8) * QSTRIDE + d], acc[j]);
        }
#pragma unroll
        for (int j = 0; j < 8; j++)
            sc[srow * 256 + kt * 64 + scb + j * 8] = acc[j] * SM_SCALE;
    }
    __syncthreads();

    const int warp = tid >> 5, lane = tid & 31;
    for (int r = warp * 4; r < warp * 4 + 4; r++) {
        float m = -INFINITY;
        for (int c = lane; c < 256; c += 32) m = fmaxf(m, sc[r * 256 + c]);
#pragma unroll
        for (int o = 16; o; o >>= 1) m = fmaxf(m, __shfl_xor_sync(0xffffffffu, m, o));
        float l = 0.f;
        for (int c = lane; c < 256; c += 32) {
            float e = expf(sc[r * 256 + c] - m);
            sc[r * 256 + c] = e;
            l += e;
        }
#pragma unroll
        for (int o = 16; o; o >>= 1) l += __shfl_xor_sync(0xffffffffu, l, o);
        if (lane == 0) row_l[r] = l;
    }
    __syncthreads();

    const int orow = tid >> 3;
    const int odb  = (tid & 7) * 12;
    float oacc[12];
#pragma unroll
    for (int j = 0; j < 12; j++) oacc[j] = 0.f;

    for (int kt = 0; kt < 4; kt++) {
        __syncthreads();
        for (int idx = tid; idx < 64 * HEADDIM; idx += 256) {
            int r = idx / HEADDIM, d = idx % HEADDIM;
            kv_s[r * QSTRIDE + d] = vb[(size_t)(kt * 64 + r) * HEADDIM + d];
        }
        __syncthreads();
        for (int c = 0; c < 64; c++) {
            float p = sc[orow * 256 + kt * 64 + c];
#pragma unroll
            for (int j = 0; j < 12; j++)
                oacc[j] = fmaf(p, kv_s[c * QSTRIDE + odb + j], oacc[j]);
        }
    }

    float invl = 1.0f / row_l[orow];
    size_t obase = (size_t)(bf * SEQ + qc * 32 + orow) * DMODEL + h * HEADDIM + odb;
#pragma unroll
    for (int j = 0; j < 12; j++)
        g_o[obase + j] = oacc[j] * invl;
}

// ============================================================================
// launch
// ============================================================================
extern "C" void kernel_launch(void* const* d_in, const int* in_sizes, int n_in,
                              void* d_out, int out_size)
{
    const float* x     = (const float*)d_in[0];
    const float* w_qkv = (const float*)d_in[1];
    const float* w_o   = (const float*)d_in[2];
    float* out = (float*)d_out;

    float *qkv_p, *o_p, *wr_p;
    cudaGetSymbolAddress((void**)&qkv_p, g_qkv);
    cudaGetSymbolAddress((void**)&o_p, g_o);
    cudaGetSymbolAddress((void**)&wr_p, g_wr);

    cudaFuncSetAttribute(gemm_tf32,
                         cudaFuncAttributeMaxDynamicSharedMemorySize, GEMM_SMEM);
    cudaFuncSetAttribute(attn_kernel,
                         cudaFuncAttributeMaxDynamicSharedMemorySize, ATTN_SMEM_BYTES);

    int n4;

    // round x -> g_o (xr), round w_qkv -> g_wr
    n4 = MTOK * DMODEL / 4;
    round_tf32_kernel<<<(n4 + 255) / 256, 256>>>((const float4*)x, (float4*)o_p, n4);
    n4 = QKV_N * DMODEL / 4;
    round_tf32_kernel<<<(n4 + 255) / 256, 256>>>((const float4*)w_qkv, (float4*)wr_p, n4);

    // 1) QKV projection: g_qkv[32768,1920] = xr @ w_qkv^T   (tf32 mma.sync)
    gemm_tf32<<<dim3(QKV_N / 128, MTOK / 256), 256, GEMM_SMEM>>>(
        o_p, wr_p, qkv_p, QKV_N, DMODEL);

    // 2) qk-norm + spatial RoPE + layout transpose
    {
        int total_warps = MTOK * NHEADS + 2 * MTOK * NGROUPS;
        normrope_kernel<<<total_warps / 8, 256>>>(qkv_p);
    }

    // 3) attention (writes g_o, overwriting xr)
    attn_kernel<<<dim3(8, NHEADS, BFRAMES), 256, ATTN_SMEM_BYTES>>>();

    // round o in-place, round w_o -> g_wr
    n4 = MTOK * DMODEL / 4;
    round_tf32_kernel<<<(n4 + 255) / 256, 256>>>((const float4*)o_p, (float4*)o_p, n4);
    n4 = DMODEL * DMODEL / 4;
    round_tf32_kernel<<<(n4 + 255) / 256, 256>>>((const float4*)w_o, (float4*)wr_p, n4);

    // 4) output projection: out[32768,1152] = o @ w_o^T   (tf32 mma.sync)
    gemm_tf32<<<dim3(DMODEL / 128, MTOK / 256), 256, GEMM_SMEM>>>(
        o_p, wr_p, out, DMODEL, DMODEL);
}

// round 4
// speedup vs baseline: 4.1595x; 2.1756x over previous
#include <cuda_runtime.h>
#include <math.h>
#include <stdint.h>

// ---------------- problem constants (fixed by setup_inputs) ----------------
#define BFRAMES   128          // B*T = 8*16
#define SEQ       256          // H*W = 16*16
#define DMODEL    1152
#define NHEADS    12
#define NGROUPS   4
#define HEADDIM   96
#define QKV_N     1920         // 12*96 + 2*4*96
#define MTOK      32768        // BFRAMES*SEQ
#define SM_SCALE  0.1020620726159658f   // 96^-0.5

// ---------------- scratch (device globals; no allocation allowed) ----------
__device__ float g_qkv[(size_t)MTOK * QKV_N];
__device__ float g_q[(size_t)BFRAMES * NHEADS * SEQ * HEADDIM];
__device__ float g_k[(size_t)BFRAMES * NGROUPS * SEQ * HEADDIM];
__device__ float g_v[(size_t)BFRAMES * NGROUPS * SEQ * HEADDIM];
__device__ float g_o[(size_t)MTOK * DMODEL];          // rounded x, then attn output
__device__ float g_wr[(size_t)QKV_N * DMODEL];        // rounded weights

// ============================================================================
// helpers
// ============================================================================
__device__ __forceinline__ uint32_t smem_u32(const void* p) {
    uint32_t a;
    asm("{ .reg .u64 t; cvta.to.shared.u64 t, %1; cvt.u32.u64 %0, t; }"
        : "=r"(a) : "l"(p));
    return a;
}

__device__ __forceinline__ void cp_async16(uint32_t saddr, const void* gptr) {
    asm volatile("cp.async.cg.shared.global [%0], [%1], 16;" :: "r"(saddr), "l"(gptr));
}

__device__ __forceinline__ void mma_tf32(float c[4], uint32_t a0, uint32_t a1,
                                         uint32_t a2, uint32_t a3,
                                         uint32_t b0, uint32_t b1) {
    asm volatile(
        "mma.sync.aligned.m16n8k8.row.col.f32.tf32.tf32.f32 "
        "{%0,%1,%2,%3}, {%4,%5,%6,%7}, {%8,%9}, {%0,%1,%2,%3};"
        : "+f"(c[0]), "+f"(c[1]), "+f"(c[2]), "+f"(c[3])
        : "r"(a0), "r"(a1), "r"(a2), "r"(a3), "r"(b0), "r"(b1));
}

__device__ __forceinline__ float rna_tf32(float x) {
    uint32_t u;
    asm("cvt.rna.tf32.f32 %0, %1;" : "=r"(u) : "f"(x));
    return __uint_as_float(u);
}

// ============================================================================
// tf32 mma.sync GEMM (NT): C[M,N] = A[M,K] * B[N,K]^T  (unchanged, R3-proven)
// ============================================================================
#define GPAD        36
#define STAGE_F     (256 * GPAD + 128 * GPAD)   // 13824 floats
#define GEMM_SMEM   (3 * STAGE_F * 4)           // 165888 bytes

__global__ __launch_bounds__(256, 1)
void gemm_tf32(const float* __restrict__ A, const float* __restrict__ B,
               float* __restrict__ C, int ldC, int K)
{
    extern __shared__ float smf[];
    const int tid    = threadIdx.x;
    const int lane   = tid & 31;
    const int wid    = tid >> 5;
    const int warp_m = wid & 3;
    const int warp_n = wid >> 2;
    const int m0 = blockIdx.y * 256;
    const int n0 = blockIdx.x * 128;
    const int ITERS = K >> 5;

    const float* Ag = A + (size_t)m0 * K;
    const float* Bg = B + (size_t)n0 * K;
    const uint32_t sbase = smem_u32(smf);

    auto load_stage = [&](int chunk, int st) {
        uint32_t abase = sbase + st * (STAGE_F * 4);
        uint32_t bbase = abase + 256 * GPAD * 4;
        const float* Ac = Ag + chunk * 32;
        const float* Bc = Bg + chunk * 32;
#pragma unroll
        for (int j = 0; j < 8; j++) {
            int idx = tid + j * 256;
            int row = idx >> 3, c = idx & 7;
            cp_async16(abase + row * (GPAD * 4) + c * 16,
                       Ac + (size_t)row * K + c * 4);
        }
#pragma unroll
        for (int j = 0; j < 4; j++) {
            int idx = tid + j * 256;
            int row = idx >> 3, c = idx & 7;
            cp_async16(bbase + row * (GPAD * 4) + c * 16,
                       Bc + (size_t)row * K + c * 4);
        }
    };

    float acc[4][8][4];
#pragma unroll
    for (int mt = 0; mt < 4; mt++)
#pragma unroll
        for (int nt = 0; nt < 8; nt++)
#pragma unroll
            for (int r = 0; r < 4; r++) acc[mt][nt][r] = 0.f;

    load_stage(0, 0);
    asm volatile("cp.async.commit_group;");
    if (ITERS > 1) load_stage(1, 1);
    asm volatile("cp.async.commit_group;");

    for (int i = 0; i < ITERS; i++) {
        const int st = i % 3;
        asm volatile("cp.async.wait_group 1;");
        __syncthreads();

        if (i + 2 < ITERS) load_stage(i + 2, (i + 2) % 3);
        asm volatile("cp.async.commit_group;");

        const float* Ab = smf + st * STAGE_F
                        + (warp_m * 64 + (lane >> 2)) * GPAD + (lane & 3);
        const float* Bb = smf + st * STAGE_F + 256 * GPAD
                        + (warp_n * 64 + (lane >> 2)) * GPAD + (lane & 3);

#pragma unroll
        for (int ks = 0; ks < 4; ks++) {
            const int k0 = ks * 8;
            uint32_t af[4][4];
#pragma unroll
            for (int mt = 0; mt < 4; mt++) {
                af[mt][0] = __float_as_uint(Ab[mt * 16 * GPAD + k0]);
                af[mt][1] = __float_as_uint(Ab[mt * 16 * GPAD + 8 * GPAD + k0]);
                af[mt][2] = __float_as_uint(Ab[mt * 16 * GPAD + k0 + 4]);
                af[mt][3] = __float_as_uint(Ab[mt * 16 * GPAD + 8 * GPAD + k0 + 4]);
            }
            uint32_t bf[8][2];
#pragma unroll
            for (int nt = 0; nt < 8; nt++) {
                bf[nt][0] = __float_as_uint(Bb[nt * 8 * GPAD + k0]);
                bf[nt][1] = __float_as_uint(Bb[nt * 8 * GPAD + k0 + 4]);
            }
#pragma unroll
            for (int mt = 0; mt < 4; mt++)
#pragma unroll
                for (int nt = 0; nt < 8; nt++)
                    mma_tf32(acc[mt][nt], af[mt][0], af[mt][1], af[mt][2], af[mt][3],
                             bf[nt][0], bf[nt][1]);
        }
        __syncthreads();
    }

#pragma unroll
    for (int mt = 0; mt < 4; mt++) {
        int row0 = m0 + warp_m * 64 + mt * 16 + (lane >> 2);
#pragma unroll
        for (int nt = 0; nt < 8; nt++) {
            int col = n0 + warp_n * 64 + nt * 8 + (lane & 3) * 2;
            float2 v0 = make_float2(acc[mt][nt][0], acc[mt][nt][1]);
            float2 v1 = make_float2(acc[mt][nt][2], acc[mt][nt][3]);
            *(float2*)(C + (size_t)row0 * ldC + col) = v0;
            *(float2*)(C + (size_t)(row0 + 8) * ldC + col) = v1;
        }
    }
}

// ============================================================================
// round fp32 -> tf32 (RNA) elementwise, vectorized
// ============================================================================
__global__ __launch_bounds__(256) void round_tf32_kernel(
    const float4* __restrict__ in, float4* __restrict__ out, int n4)
{
    int i = blockIdx.x * blockDim.x + threadIdx.x;
    if (i >= n4) return;
    float4 v = in[i];
    out[i] = make_float4(rna_tf32(v.x), rna_tf32(v.y), rna_tf32(v.z), rna_tf32(v.w));
}

// ============================================================================
// norm + RoPE + layout transpose; now emits tf32-ROUNDED q/k/v for the
// tensor-core attention kernel.
// ============================================================================
__global__ __launch_bounds__(256) void normrope_kernel(const float* __restrict__ qkv)
{
    const int NQv = MTOK * NHEADS;
    const int NKv = MTOK * NGROUPS;
    int wid  = (blockIdx.x * blockDim.x + threadIdx.x) >> 5;
    int lane = threadIdx.x & 31;
    if (wid >= NQv + 2 * NKv) return;

    const float* src;
    float* dst;
    int t;
    bool do_norm_rope = true;

    if (wid < NQv) {
        t = wid / NHEADS; int h = wid % NHEADS;
        src = qkv + (size_t)t * QKV_N + h * HEADDIM;
        int bf = t >> 8, s = t & 255;
        dst = g_q + ((size_t)(bf * NHEADS + h) * SEQ + s) * HEADDIM;
    } else if (wid < NQv + NKv) {
        int v = wid - NQv; t = v / NGROUPS; int g = v % NGROUPS;
        src = qkv + (size_t)t * QKV_N + DMODEL + g * HEADDIM;
        int bf = t >> 8, s = t & 255;
        dst = g_k + ((size_t)(bf * NGROUPS + g) * SEQ + s) * HEADDIM;
    } else {
        int v = wid - NQv - NKv; t = v / NGROUPS; int g = v % NGROUPS;
        src = qkv + (size_t)t * QKV_N + DMODEL + NGROUPS * HEADDIM + g * HEADDIM;
        int bf = t >> 8, s = t & 255;
        dst = g_v + ((size_t)(bf * NGROUPS + g) * SEQ + s) * HEADDIM;
        do_norm_rope = false;
    }

    float x0 = src[lane], x1 = src[lane + 32], x2 = src[lane + 64];

    if (do_norm_rope) {
        float ss = fmaf(x0, x0, fmaf(x1, x1, x2 * x2));
#pragma unroll
        for (int o = 16; o; o >>= 1) ss += __shfl_xor_sync(0xffffffffu, ss, o);
        float inv = 1.0f / fmaxf(sqrtf(ss), 1e-10f);
        x0 *= inv; x1 *= inv; x2 *= inv;

        int s = t & 255;
        float pos = (float)((s >> 4) + (s & 15));
        int i = lane & 15;
        float a = __shfl_sync(0xffffffffu, x0, 2 * i);
        float b = __shfl_sync(0xffffffffu, x0, 2 * i + 1);
        float invf = exp2f(-(float)i * 0.8304820237218406f);
        float ang = pos * invf;
        float sn, cs;
        sincosf(ang, &sn, &cs);
        x0 = (lane < 16) ? fmaf(a, cs, -b * sn) : fmaf(a, sn, b * cs);
    }

    dst[lane]      = rna_tf32(x0);
    dst[lane + 32] = rna_tf32(x1);
    dst[lane + 64] = rna_tf32(x2);
}

// ============================================================================
// Flash attention with tf32 mma.sync.
// CTA = (q-half of 128 rows, head, bf); 8 warps x 16 q-rows.
// Streams 4 chunks of 64 keys; online softmax in mma accumulator layout.
// smem strides chosen for conflict-free B-fragment LDS.
// ============================================================================
#define KSTRIDE 100
#define VSTRIDE 104
#define PSTRIDE 68
#define ATTN_SMEM_BYTES ((64 * KSTRIDE + 64 * VSTRIDE + 128 * PSTRIDE) * 4)  // 87040

__global__ __launch_bounds__(256, 1) void attn_kernel()
{
    extern __shared__ float sm[];
    float* Ks = sm;
    float* Vs = Ks + 64 * KSTRIDE;
    float* Ps = Vs + 64 * VSTRIDE;

    const int tid  = threadIdx.x;
    const int lane = tid & 31;
    const int wid  = tid >> 5;
    const int half = blockIdx.x;      // 0..1
    const int h    = blockIdx.y;      // 0..11
    const int bf   = blockIdx.z;      // 0..127
    const int g    = h / 3;

    const float* Qg = g_q + ((size_t)(bf * NHEADS + h) * SEQ + half * 128 + wid * 16) * HEADDIM;
    const float* Kg = g_k + (size_t)(bf * NGROUPS + g) * SEQ * HEADDIM;
    const float* Vg = g_v + (size_t)(bf * NGROUPS + g) * SEQ * HEADDIM;

    // Q fragments for 12 k-steps (held for whole CTA lifetime)
    uint32_t qf[12][4];
    {
        const float* q0 = Qg + (lane >> 2) * HEADDIM;
        const float* q1 = Qg + ((lane >> 2) + 8) * HEADDIM;
#pragma unroll
        for (int j = 0; j < 12; j++) {
            int c = j * 8 + (lane & 3);
            qf[j][0] = __float_as_uint(q0[c]);
            qf[j][1] = __float_as_uint(q1[c]);
            qf[j][2] = __float_as_uint(q0[c + 4]);
            qf[j][3] = __float_as_uint(q1[c + 4]);
        }
    }

    float m_a = -INFINITY, m_b = -INFINITY;
    float l_a = 0.f, l_b = 0.f;
    float oacc[12][4];
#pragma unroll
    for (int nt = 0; nt < 12; nt++)
#pragma unroll
        for (int r = 0; r < 4; r++) oacc[nt][r] = 0.f;

    float* Pw = Ps + wid * 16 * PSTRIDE;

    for (int kt = 0; kt < 4; kt++) {
        __syncthreads();
        // cooperative load of K,V chunk [64][96]
        {
            const float* Kc = Kg + (size_t)kt * 64 * HEADDIM;
            const float* Vc = Vg + (size_t)kt * 64 * HEADDIM;
#pragma unroll
            for (int it = 0; it < 6; it++) {
                int i = tid + it * 256;          // 0..1535
                int r = i / 24, c = (i % 24) * 4;
                *(float4*)(Ks + r * KSTRIDE + c) = *(const float4*)(Kc + r * HEADDIM + c);
                *(float4*)(Vs + r * VSTRIDE + c) = *(const float4*)(Vc + r * HEADDIM + c);
            }
        }
        __syncthreads();

        // ---- S = Q K^T (scaled) ----
        float sacc[8][4];
#pragma unroll
        for (int nt = 0; nt < 8; nt++)
#pragma unroll
            for (int r = 0; r < 4; r++) sacc[nt][r] = 0.f;

#pragma unroll
        for (int j = 0; j < 12; j++) {
            const float* kb = Ks + (lane >> 2) * KSTRIDE + j * 8 + (lane & 3);
#pragma unroll
            for (int nt = 0; nt < 8; nt++) {
                uint32_t b0 = __float_as_uint(kb[nt * 8 * KSTRIDE]);
                uint32_t b1 = __float_as_uint(kb[nt * 8 * KSTRIDE + 4]);
                mma_tf32(sacc[nt], qf[j][0], qf[j][1], qf[j][2], qf[j][3], b0, b1);
            }
        }

        // ---- online softmax ----
        float tmax_a = -INFINITY, tmax_b = -INFINITY;
#pragma unroll
        for (int nt = 0; nt < 8; nt++) {
#pragma unroll
            for (int r = 0; r < 4; r++) sacc[nt][r] *= SM_SCALE;
            tmax_a = fmaxf(tmax_a, fmaxf(sacc[nt][0], sacc[nt][1]));
            tmax_b = fmaxf(tmax_b, fmaxf(sacc[nt][2], sacc[nt][3]));
        }
        tmax_a = fmaxf(tmax_a, __shfl_xor_sync(0xffffffffu, tmax_a, 1));
        tmax_a = fmaxf(tmax_a, __shfl_xor_sync(0xffffffffu, tmax_a, 2));
        tmax_b = fmaxf(tmax_b, __shfl_xor_sync(0xffffffffu, tmax_b, 1));
        tmax_b = fmaxf(tmax_b, __shfl_xor_sync(0xffffffffu, tmax_b, 2));

        float mn_a = fmaxf(m_a, tmax_a);
        float mn_b = fmaxf(m_b, tmax_b);
        float al_a = __expf(m_a - mn_a);
        float al_b = __expf(m_b - mn_b);
        m_a = mn_a; m_b = mn_b;

        __syncwarp();   // previous chunk's P reads are done before overwrite

        float sum_a = 0.f, sum_b = 0.f;
        {
            int r0 = (lane >> 2);
            int cc = 2 * (lane & 3);
#pragma unroll
            for (int nt = 0; nt < 8; nt++) {
                float p0 = __expf(sacc[nt][0] - mn_a);
                float p1 = __expf(sacc[nt][1] - mn_a);
                float p2 = __expf(sacc[nt][2] - mn_b);
                float p3 = __expf(sacc[nt][3] - mn_b);
                sum_a += p0 + p1;
                sum_b += p2 + p3;
                int col = nt * 8 + cc;
                *(float2*)(Pw + r0 * PSTRIDE + col) =
                    make_float2(rna_tf32(p0), rna_tf32(p1));
                *(float2*)(Pw + (r0 + 8) * PSTRIDE + col) =
                    make_float2(rna_tf32(p2), rna_tf32(p3));
            }
        }
        sum_a += __shfl_xor_sync(0xffffffffu, sum_a, 1);
        sum_a += __shfl_xor_sync(0xffffffffu, sum_a, 2);
        sum_b += __shfl_xor_sync(0xffffffffu, sum_b, 1);
        sum_b += __shfl_xor_sync(0xffffffffu, sum_b, 2);
        l_a = l_a * al_a + sum_a;
        l_b = l_b * al_b + sum_b;

#pragma unroll
        for (int nt = 0; nt < 12; nt++) {
            oacc[nt][0] *= al_a; oacc[nt][1] *= al_a;
            oacc[nt][2] *= al_b; oacc[nt][3] *= al_b;
        }

        __syncwarp();   // P writes visible to all lanes of this warp

        // ---- O += P V ----
#pragma unroll
        for (int j = 0; j < 8; j++) {
            const float* pa = Pw + (lane >> 2) * PSTRIDE + j * 8 + (lane & 3);
            uint32_t a0 = __float_as_uint(pa[0]);
            uint32_t a1 = __float_as_uint(pa[8 * PSTRIDE]);
            uint32_t a2 = __float_as_uint(pa[4]);
            uint32_t a3 = __float_as_uint(pa[8 * PSTRIDE + 4]);
            const float* vb = Vs + (j * 8 + (lane & 3)) * VSTRIDE + (lane >> 2);
#pragma unroll
            for (int nt = 0; nt < 12; nt++) {
                uint32_t b0 = __float_as_uint(vb[nt * 8]);
                uint32_t b1 = __float_as_uint(vb[nt * 8 + 4 * VSTRIDE]);
                mma_tf32(oacc[nt], a0, a1, a2, a3, b0, b1);
            }
        }
    }

    // ---- epilogue: normalize, round to tf32, store to g_o ----
    float invla = 1.0f / l_a;
    float invlb = 1.0f / l_b;
    int row0 = half * 128 + wid * 16 + (lane >> 2);
    float* o0 = g_o + (size_t)(bf * SEQ + row0) * DMODEL + h * HEADDIM;
    float* o1 = g_o + (size_t)(bf * SEQ + row0 + 8) * DMODEL + h * HEADDIM;
#pragma unroll
    for (int nt = 0; nt < 12; nt++) {
        int col = nt * 8 + 2 * (lane & 3);
        *(float2*)(o0 + col) = make_float2(rna_tf32(oacc[nt][0] * invla),
                                           rna_tf32(oacc[nt][1] * invla));
        *(float2*)(o1 + col) = make_float2(rna_tf32(oacc[nt][2] * invlb),
                                           rna_tf32(oacc[nt][3] * invlb));
    }
}

// ============================================================================
// launch
// ============================================================================
extern "C" void kernel_launch(void* const* d_in, const int* in_sizes, int n_in,
                              void* d_out, int out_size)
{
    const float* x     = (const float*)d_in[0];
    const float* w_qkv = (const float*)d_in[1];
    const float* w_o   = (const float*)d_in[2];
    float* out = (float*)d_out;

    float *qkv_p, *o_p, *wr_p;
    cudaGetSymbolAddress((void**)&qkv_p, g_qkv);
    cudaGetSymbolAddress((void**)&o_p, g_o);
    cudaGetSymbolAddress((void**)&wr_p, g_wr);

    cudaFuncSetAttribute(gemm_tf32,
                         cudaFuncAttributeMaxDynamicSharedMemorySize, GEMM_SMEM);
    cudaFuncSetAttribute(attn_kernel,
                         cudaFuncAttributeMaxDynamicSharedMemorySize, ATTN_SMEM_BYTES);

    int n4;

    // round x -> g_o (xr), round w_qkv -> g_wr
    n4 = MTOK * DMODEL / 4;
    round_tf32_kernel<<<(n4 + 255) / 256, 256>>>((const float4*)x, (float4*)o_p, n4);
    n4 = QKV_N * DMODEL / 4;
    round_tf32_kernel<<<(n4 + 255) / 256, 256>>>((const float4*)w_qkv, (float4*)wr_p, n4);

    // 1) QKV projection: g_qkv[32768,1920] = xr @ w_qkv^T   (tf32 mma.sync)
    gemm_tf32<<<dim3(QKV_N / 128, MTOK / 256), 256, GEMM_SMEM>>>(
        o_p, wr_p, qkv_p, QKV_N, DMODEL);

    // 2) qk-norm + spatial RoPE + transpose (emits tf32-rounded q/k/v)
    {
        int total_warps = MTOK * NHEADS + 2 * MTOK * NGROUPS;
        normrope_kernel<<<total_warps / 8, 256>>>(qkv_p);
    }

    // 3) flash attention (tf32 mma.sync; writes tf32-rounded g_o)
    attn_kernel<<<dim3(2, NHEADS, BFRAMES), 256, ATTN_SMEM_BYTES>>>();

    // round w_o -> g_wr (o already rounded by attention epilogue)
    n4 = DMODEL * DMODEL / 4;
    round_tf32_kernel<<<(n4 + 255) / 256, 256>>>((const float4*)w_o, (float4*)wr_p, n4);

    // 4) output projection: out[32768,1152] = o @ w_o^T   (tf32 mma.sync)
    gemm_tf32<<<dim3(DMODEL / 128, MTOK / 256), 256, GEMM_SMEM>>>(
        o_p, wr_p, out, DMODEL, DMODEL);
}

// round 5
// speedup vs baseline: 5.8407x; 1.4042x over previous
#include <cuda_runtime.h>
#include <cuda_fp16.h>
#include <math.h>
#include <stdint.h>

// ---------------- problem constants (fixed by setup_inputs) ----------------
#define BFRAMES   128          // B*T = 8*16
#define SEQ       256          // H*W = 16*16
#define DMODEL    1152
#define NHEADS    12
#define NGROUPS   4
#define HEADDIM   96
#define QKV_N     1920         // 12*96 + 2*4*96
#define MTOK      32768        // BFRAMES*SEQ
#define SM_SCALE  0.1020620726159658f   // 96^-0.5

// ---------------- scratch (device globals; no allocation allowed) ----------
__device__ float  g_qkv[(size_t)MTOK * QKV_N];
__device__ float  g_q[(size_t)BFRAMES * NHEADS * SEQ * HEADDIM];
__device__ float  g_k[(size_t)BFRAMES * NGROUPS * SEQ * HEADDIM];
__device__ float  g_v[(size_t)BFRAMES * NGROUPS * SEQ * HEADDIM];
__device__ __half g_xh[(size_t)MTOK * DMODEL];     // fp16 x
__device__ __half g_oh[(size_t)MTOK * DMODEL];     // fp16 attention output
__device__ __half g_wh[(size_t)QKV_N * DMODEL];    // fp16 weights (reused)

// ============================================================================
// helpers
// ============================================================================
__device__ __forceinline__ uint32_t smem_u32(const void* p) {
    uint32_t a;
    asm("{ .reg .u64 t; cvta.to.shared.u64 t, %1; cvt.u32.u64 %0, t; }"
        : "=r"(a) : "l"(p));
    return a;
}

__device__ __forceinline__ void cp_async16(uint32_t saddr, const void* gptr) {
    asm volatile("cp.async.cg.shared.global [%0], [%1], 16;" :: "r"(saddr), "l"(gptr));
}

__device__ __forceinline__ void mma_tf32(float c[4], uint32_t a0, uint32_t a1,
                                         uint32_t a2, uint32_t a3,
                                         uint32_t b0, uint32_t b1) {
    asm volatile(
        "mma.sync.aligned.m16n8k8.row.col.f32.tf32.tf32.f32 "
        "{%0,%1,%2,%3}, {%4,%5,%6,%7}, {%8,%9}, {%0,%1,%2,%3};"
        : "+f"(c[0]), "+f"(c[1]), "+f"(c[2]), "+f"(c[3])
        : "r"(a0), "r"(a1), "r"(a2), "r"(a3), "r"(b0), "r"(b1));
}

__device__ __forceinline__ void mma_f16(float c[4], const uint32_t a[4],
                                        const uint32_t b[2]) {
    asm volatile(
        "mma.sync.aligned.m16n8k16.row.col.f32.f16.f16.f32 "
        "{%0,%1,%2,%3}, {%4,%5,%6,%7}, {%8,%9}, {%0,%1,%2,%3};"
        : "+f"(c[0]), "+f"(c[1]), "+f"(c[2]), "+f"(c[3])
        : "r"(a[0]), "r"(a[1]), "r"(a[2]), "r"(a[3]), "r"(b[0]), "r"(b[1]));
}

__device__ __forceinline__ void ldsm4(uint32_t r[4], uint32_t addr) {
    asm volatile("ldmatrix.sync.aligned.m8n8.x4.shared.b16 {%0,%1,%2,%3}, [%4];"
                 : "=r"(r[0]), "=r"(r[1]), "=r"(r[2]), "=r"(r[3]) : "r"(addr));
}

__device__ __forceinline__ float rna_tf32(float x) {
    uint32_t u;
    asm("cvt.rna.tf32.f32 %0, %1;" : "=r"(u) : "f"(x));
    return __uint_as_float(u);
}

// ============================================================================
// fp16 mma.sync GEMM (NT): C[M,N] = A[M,K] * B[N,K]^T, A/B fp16 K-major,
// fp32 accumulate. CTA tile 256x128, BK=32, 4-stage cp.async, 8 warps
// (warp tile 64x64), ldmatrix.x4 fragment loads.
// Smem rows padded to 40 halves (80B) -> all LDSM phases conflict-free.
// ============================================================================
#define HSTR      40
#define STAGE_H   ((256 + 128) * HSTR)       // 15360 halves
#define NSTAGE    4
#define GEMM_SMEM (NSTAGE * STAGE_H * 2)     // 122880 bytes

__global__ __launch_bounds__(256, 1)
void gemm_f16(const __half* __restrict__ A, const __half* __restrict__ B,
              float* __restrict__ C, int ldC, int K)
{
    extern __shared__ __half smh[];
    const int tid    = threadIdx.x;
    const int lane   = tid & 31;
    const int wid    = tid >> 5;
    const int warp_m = wid & 3;     // 4 warps over M (64 rows each)
    const int warp_n = wid >> 2;    // 2 warps over N (64 cols each)
    const int m0 = blockIdx.y * 256;
    const int n0 = blockIdx.x * 128;
    const int ITERS = K >> 5;

    const __half* Ag = A + (size_t)m0 * K;
    const __half* Bg = B + (size_t)n0 * K;
    const uint32_t sbase = smem_u32(smh);

    auto load_stage = [&](int chunk, int st) {
        uint32_t abase = sbase + st * (STAGE_H * 2);
        uint32_t bbase = abase + 256 * (HSTR * 2);
        const __half* Ac = Ag + chunk * 32;
        const __half* Bc = Bg + chunk * 32;
#pragma unroll
        for (int j = 0; j < 4; j++) {            // A: 256 rows x 4 chunks of 16B
            int idx = tid + j * 256;
            int row = idx >> 2, c = idx & 3;
            cp_async16(abase + row * (HSTR * 2) + c * 16,
                       Ac + (size_t)row * K + c * 8);
        }
#pragma unroll
        for (int j = 0; j < 2; j++) {            // B: 128 rows x 4 chunks of 16B
            int idx = tid + j * 256;
            int row = idx >> 2, c = idx & 3;
            cp_async16(bbase + row * (HSTR * 2) + c * 16,
                       Bc + (size_t)row * K + c * 8);
        }
    };

    float acc[4][8][4];
#pragma unroll
    for (int mt = 0; mt < 4; mt++)
#pragma unroll
        for (int nt = 0; nt < 8; nt++)
#pragma unroll
            for (int r = 0; r < 4; r++) acc[mt][nt][r] = 0.f;

    // ldmatrix per-thread row/col offsets (halves), within a stage
    const int arow = warp_m * 64 + (lane & 15);          // + mt*16
    const int acol = (lane >> 4) * 8;                    // + kstep*16
    const int brow = warp_n * 64 + (lane & 7) + (lane >> 4) * 8;  // + ntp*16
    const int bcol = ((lane >> 3) & 1) * 8;              // + kstep*16

    load_stage(0, 0);
    asm volatile("cp.async.commit_group;");
    if (ITERS > 1) load_stage(1, 1);
    asm volatile("cp.async.commit_group;");
    if (ITERS > 2) load_stage(2, 2);
    asm volatile("cp.async.commit_group;");

    for (int i = 0; i < ITERS; i++) {
        const int st = i & 3;
        asm volatile("cp.async.wait_group 2;");
        __syncthreads();

        if (i + 3 < ITERS) load_stage(i + 3, (i + 3) & 3);
        asm volatile("cp.async.commit_group;");

        uint32_t abase = sbase + st * (STAGE_H * 2);
        uint32_t bbase = abase + 256 * (HSTR * 2);

#pragma unroll
        for (int kstep = 0; kstep < 2; kstep++) {
            uint32_t af[4][4];
#pragma unroll
            for (int mt = 0; mt < 4; mt++)
                ldsm4(af[mt], abase + ((arow + mt * 16) * HSTR
                                       + kstep * 16 + acol) * 2);
            uint32_t bf[8][2];
#pragma unroll
            for (int ntp = 0; ntp < 4; ntp++) {
                uint32_t r[4];
                ldsm4(r, bbase + ((brow + ntp * 16) * HSTR
                                  + kstep * 16 + bcol) * 2);
                bf[2 * ntp][0] = r[0]; bf[2 * ntp][1] = r[1];
                bf[2 * ntp + 1][0] = r[2]; bf[2 * ntp + 1][1] = r[3];
            }
#pragma unroll
            for (int mt = 0; mt < 4; mt++)
#pragma unroll
                for (int nt = 0; nt < 8; nt++)
                    mma_f16(acc[mt][nt], af[mt], bf[nt]);
        }
        __syncthreads();
    }

    // ---- epilogue (fp32) ----
#pragma unroll
    for (int mt = 0; mt < 4; mt++) {
        int row0 = m0 + warp_m * 64 + mt * 16 + (lane >> 2);
#pragma unroll
        for (int nt = 0; nt < 8; nt++) {
            int col = n0 + warp_n * 64 + nt * 8 + (lane & 3) * 2;
            float2 v0 = make_float2(acc[mt][nt][0], acc[mt][nt][1]);
            float2 v1 = make_float2(acc[mt][nt][2], acc[mt][nt][3]);
            *(float2*)(C + (size_t)row0 * ldC + col) = v0;
            *(float2*)(C + (size_t)(row0 + 8) * ldC + col) = v1;
        }
    }
}

// ============================================================================
// convert fp32 -> fp16 (RN), 8 elems per thread, 16B stores
// ============================================================================
__global__ __launch_bounds__(256) void f32_to_f16_kernel(
    const float4* __restrict__ in, uint4* __restrict__ out, int n8)
{
    int i = blockIdx.x * blockDim.x + threadIdx.x;
    if (i >= n8) return;
    float4 a = in[2 * i], b = in[2 * i + 1];
    __half2 h0 = __float22half2_rn(make_float2(a.x, a.y));
    __half2 h1 = __float22half2_rn(make_float2(a.z, a.w));
    __half2 h2 = __float22half2_rn(make_float2(b.x, b.y));
    __half2 h3 = __float22half2_rn(make_float2(b.z, b.w));
    uint4 o;
    o.x = *(uint32_t*)&h0; o.y = *(uint32_t*)&h1;
    o.z = *(uint32_t*)&h2; o.w = *(uint32_t*)&h3;
    out[i] = o;
}

// ============================================================================
// norm + RoPE + layout transpose; emits tf32-rounded q/k/v (unchanged)
// ============================================================================
__global__ __launch_bounds__(256) void normrope_kernel(const float* __restrict__ qkv)
{
    const int NQv = MTOK * NHEADS;
    const int NKv = MTOK * NGROUPS;
    int wid  = (blockIdx.x * blockDim.x + threadIdx.x) >> 5;
    int lane = threadIdx.x & 31;
    if (wid >= NQv + 2 * NKv) return;

    const float* src;
    float* dst;
    int t;
    bool do_norm_rope = true;

    if (wid < NQv) {
        t = wid / NHEADS; int h = wid % NHEADS;
        src = qkv + (size_t)t * QKV_N + h * HEADDIM;
        int bf = t >> 8, s = t & 255;
        dst = g_q + ((size_t)(bf * NHEADS + h) * SEQ + s) * HEADDIM;
    } else if (wid < NQv + NKv) {
        int v = wid - NQv; t = v / NGROUPS; int g = v % NGROUPS;
        src = qkv + (size_t)t * QKV_N + DMODEL + g * HEADDIM;
        int bf = t >> 8, s = t & 255;
        dst = g_k + ((size_t)(bf * NGROUPS + g) * SEQ + s) * HEADDIM;
    } else {
        int v = wid - NQv - NKv; t = v / NGROUPS; int g = v % NGROUPS;
        src = qkv + (size_t)t * QKV_N + DMODEL + NGROUPS * HEADDIM + g * HEADDIM;
        int bf = t >> 8, s = t & 255;
        dst = g_v + ((size_t)(bf * NGROUPS + g) * SEQ + s) * HEADDIM;
        do_norm_rope = false;
    }

    float x0 = src[lane], x1 = src[lane + 32], x2 = src[lane + 64];

    if (do_norm_rope) {
        float ss = fmaf(x0, x0, fmaf(x1, x1, x2 * x2));
#pragma unroll
        for (int o = 16; o; o >>= 1) ss += __shfl_xor_sync(0xffffffffu, ss, o);
        float inv = 1.0f / fmaxf(sqrtf(ss), 1e-10f);
        x0 *= inv; x1 *= inv; x2 *= inv;

        int s = t & 255;
        float pos = (float)((s >> 4) + (s & 15));
        int i = lane & 15;
        float a = __shfl_sync(0xffffffffu, x0, 2 * i);
        float b = __shfl_sync(0xffffffffu, x0, 2 * i + 1);
        float invf = exp2f(-(float)i * 0.8304820237218406f);
        float ang = pos * invf;
        float sn, cs;
        sincosf(ang, &sn, &cs);
        x0 = (lane < 16) ? fmaf(a, cs, -b * sn) : fmaf(a, sn, b * cs);
    }

    dst[lane]      = rna_tf32(x0);
    dst[lane + 32] = rna_tf32(x1);
    dst[lane + 64] = rna_tf32(x2);
}

// ============================================================================
// Flash attention with tf32 mma.sync (R4-proven); epilogue now emits fp16 g_oh
// ============================================================================
#define KSTRIDE 100
#define VSTRIDE 104
#define PSTRIDE 68
#define ATTN_SMEM_BYTES ((64 * KSTRIDE + 64 * VSTRIDE + 128 * PSTRIDE) * 4)  // 87040

__global__ __launch_bounds__(256, 1) void attn_kernel()
{
    extern __shared__ float sm[];
    float* Ks = sm;
    float* Vs = Ks + 64 * KSTRIDE;
    float* Ps = Vs + 64 * VSTRIDE;

    const int tid  = threadIdx.x;
    const int lane = tid & 31;
    const int wid  = tid >> 5;
    const int half = blockIdx.x;
    const int h    = blockIdx.y;
    const int bf   = blockIdx.z;
    const int g    = h / 3;

    const float* Qg = g_q + ((size_t)(bf * NHEADS + h) * SEQ + half * 128 + wid * 16) * HEADDIM;
    const float* Kg = g_k + (size_t)(bf * NGROUPS + g) * SEQ * HEADDIM;
    const float* Vg = g_v + (size_t)(bf * NGROUPS + g) * SEQ * HEADDIM;

    uint32_t qf[12][4];
    {
        const float* q0 = Qg + (lane >> 2) * HEADDIM;
        const float* q1 = Qg + ((lane >> 2) + 8) * HEADDIM;
#pragma unroll
        for (int j = 0; j < 12; j++) {
            int c = j * 8 + (lane & 3);
            qf[j][0] = __float_as_uint(q0[c]);
            qf[j][1] = __float_as_uint(q1[c]);
            qf[j][2] = __float_as_uint(q0[c + 4]);
            qf[j][3] = __float_as_uint(q1[c + 4]);
        }
    }

    float m_a = -INFINITY, m_b = -INFINITY;
    float l_a = 0.f, l_b = 0.f;
    float oacc[12][4];
#pragma unroll
    for (int nt = 0; nt < 12; nt++)
#pragma unroll
        for (int r = 0; r < 4; r++) oacc[nt][r] = 0.f;

    float* Pw = Ps + wid * 16 * PSTRIDE;

    for (int kt = 0; kt < 4; kt++) {
        __syncthreads();
        {
            const float* Kc = Kg + (size_t)kt * 64 * HEADDIM;
            const float* Vc = Vg + (size_t)kt * 64 * HEADDIM;
#pragma unroll
            for (int it = 0; it < 6; it++) {
                int i = tid + it * 256;
                int r = i / 24, c = (i % 24) * 4;
                *(float4*)(Ks + r * KSTRIDE + c) = *(const float4*)(Kc + r * HEADDIM + c);
                *(float4*)(Vs + r * VSTRIDE + c) = *(const float4*)(Vc + r * HEADDIM + c);
            }
        }
        __syncthreads();

        float sacc[8][4];
#pragma unroll
        for (int nt = 0; nt < 8; nt++)
#pragma unroll
            for (int r = 0; r < 4; r++) sacc[nt][r] = 0.f;

#pragma unroll
        for (int j = 0; j < 12; j++) {
            const float* kb = Ks + (lane >> 2) * KSTRIDE + j * 8 + (lane & 3);
#pragma unroll
            for (int nt = 0; nt < 8; nt++) {
                uint32_t b0 = __float_as_uint(kb[nt * 8 * KSTRIDE]);
                uint32_t b1 = __float_as_uint(kb[nt * 8 * KSTRIDE + 4]);
                mma_tf32(sacc[nt], qf[j][0], qf[j][1], qf[j][2], qf[j][3], b0, b1);
            }
        }

        float tmax_a = -INFINITY, tmax_b = -INFINITY;
#pragma unroll
        for (int nt = 0; nt < 8; nt++) {
#pragma unroll
            for (int r = 0; r < 4; r++) sacc[nt][r] *= SM_SCALE;
            tmax_a = fmaxf(tmax_a, fmaxf(sacc[nt][0], sacc[nt][1]));
            tmax_b = fmaxf(tmax_b, fmaxf(sacc[nt][2], sacc[nt][3]));
        }
        tmax_a = fmaxf(tmax_a, __shfl_xor_sync(0xffffffffu, tmax_a, 1));
        tmax_a = fmaxf(tmax_a, __shfl_xor_sync(0xffffffffu, tmax_a, 2));
        tmax_b = fmaxf(tmax_b, __shfl_xor_sync(0xffffffffu, tmax_b, 1));
        tmax_b = fmaxf(tmax_b, __shfl_xor_sync(0xffffffffu, tmax_b, 2));

        float mn_a = fmaxf(m_a, tmax_a);
        float mn_b = fmaxf(m_b, tmax_b);
        float al_a = __expf(m_a - mn_a);
        float al_b = __expf(m_b - mn_b);
        m_a = mn_a; m_b = mn_b;

        __syncwarp();

        float sum_a = 0.f, sum_b = 0.f;
        {
            int r0 = (lane >> 2);
            int cc = 2 * (lane & 3);
#pragma unroll
            for (int nt = 0; nt < 8; nt++) {
                float p0 = __expf(sacc[nt][0] - mn_a);
                float p1 = __expf(sacc[nt][1] - mn_a);
                float p2 = __expf(sacc[nt][2] - mn_b);
                float p3 = __expf(sacc[nt][3] - mn_b);
                sum_a += p0 + p1;
                sum_b += p2 + p3;
                int col = nt * 8 + cc;
                *(float2*)(Pw + r0 * PSTRIDE + col) =
                    make_float2(rna_tf32(p0), rna_tf32(p1));
                *(float2*)(Pw + (r0 + 8) * PSTRIDE + col) =
                    make_float2(rna_tf32(p2), rna_tf32(p3));
            }
        }
        sum_a += __shfl_xor_sync(0xffffffffu, sum_a, 1);
        sum_a += __shfl_xor_sync(0xffffffffu, sum_a, 2);
        sum_b += __shfl_xor_sync(0xffffffffu, sum_b, 1);
        sum_b += __shfl_xor_sync(0xffffffffu, sum_b, 2);
        l_a = l_a * al_a + sum_a;
        l_b = l_b * al_b + sum_b;

#pragma unroll
        for (int nt = 0; nt < 12; nt++) {
            oacc[nt][0] *= al_a; oacc[nt][1] *= al_a;
            oacc[nt][2] *= al_b; oacc[nt][3] *= al_b;
        }

        __syncwarp();

#pragma unroll
        for (int j = 0; j < 8; j++) {
            const float* pa = Pw + (lane >> 2) * PSTRIDE + j * 8 + (lane & 3);
            uint32_t a0 = __float_as_uint(pa[0]);
            uint32_t a1 = __float_as_uint(pa[8 * PSTRIDE]);
            uint32_t a2 = __float_as_uint(pa[4]);
            uint32_t a3 = __float_as_uint(pa[8 * PSTRIDE + 4]);
            const float* vb = Vs + (j * 8 + (lane & 3)) * VSTRIDE + (lane >> 2);
#pragma unroll
            for (int nt = 0; nt < 12; nt++) {
                uint32_t b0 = __float_as_uint(vb[nt * 8]);
                uint32_t b1 = __float_as_uint(vb[nt * 8 + 4 * VSTRIDE]);
                mma_tf32(oacc[nt], a0, a1, a2, a3, b0, b1);
            }
        }
    }

    // ---- epilogue: normalize, convert to fp16, store to g_oh ----
    float invla = 1.0f / l_a;
    float invlb = 1.0f / l_b;
    int row0 = half * 128 + wid * 16 + (lane >> 2);
    __half* o0 = g_oh + (size_t)(bf * SEQ + row0) * DMODEL + h * HEADDIM;
    __half* o1 = g_oh + (size_t)(bf * SEQ + row0 + 8) * DMODEL + h * HEADDIM;
#pragma unroll
    for (int nt = 0; nt < 12; nt++) {
        int col = nt * 8 + 2 * (lane & 3);
        *(__half2*)(o0 + col) = __float22half2_rn(
            make_float2(oacc[nt][0] * invla, oacc[nt][1] * invla));
        *(__half2*)(o1 + col) = __float22half2_rn(
            make_float2(oacc[nt][2] * invlb, oacc[nt][3] * invlb));
    }
}

// ============================================================================
// launch
// ============================================================================
extern "C" void kernel_launch(void* const* d_in, const int* in_sizes, int n_in,
                              void* d_out, int out_size)
{
    const float* x     = (const float*)d_in[0];
    const float* w_qkv = (const float*)d_in[1];
    const float* w_o   = (const float*)d_in[2];
    float* out = (float*)d_out;

    float *qkv_p;
    __half *xh_p, *oh_p, *wh_p;
    cudaGetSymbolAddress((void**)&qkv_p, g_qkv);
    cudaGetSymbolAddress((void**)&xh_p, g_xh);
    cudaGetSymbolAddress((void**)&oh_p, g_oh);
    cudaGetSymbolAddress((void**)&wh_p, g_wh);

    cudaFuncSetAttribute(gemm_f16,
                         cudaFuncAttributeMaxDynamicSharedMemorySize, GEMM_SMEM);
    cudaFuncSetAttribute(attn_kernel,
                         cudaFuncAttributeMaxDynamicSharedMemorySize, ATTN_SMEM_BYTES);

    int n8;

    // convert x -> fp16, w_qkv -> fp16
    n8 = MTOK * DMODEL / 8;
    f32_to_f16_kernel<<<(n8 + 255) / 256, 256>>>((const float4*)x, (uint4*)xh_p, n8);
    n8 = QKV_N * DMODEL / 8;
    f32_to_f16_kernel<<<(n8 + 255) / 256, 256>>>((const float4*)w_qkv, (uint4*)wh_p, n8);

    // 1) QKV projection: g_qkv[32768,1920] = xh @ w_qkv^T  (fp16 mma, fp32 acc)
    gemm_f16<<<dim3(QKV_N / 128, MTOK / 256), 256, GEMM_SMEM>>>(
        xh_p, wh_p, qkv_p, QKV_N, DMODEL);

    // 2) qk-norm + spatial RoPE + transpose (tf32-rounded q/k/v)
    {
        int total_warps = MTOK * NHEADS + 2 * MTOK * NGROUPS;
        normrope_kernel<<<total_warps / 8, 256>>>(qkv_p);
    }

    // 3) flash attention (tf32 mma; writes fp16 g_oh)
    attn_kernel<<<dim3(2, NHEADS, BFRAMES), 256, ATTN_SMEM_BYTES>>>();

    // convert w_o -> fp16
    n8 = DMODEL * DMODEL / 8;
    f32_to_f16_kernel<<<(n8 + 255) / 256, 256>>>((const float4*)w_o, (uint4*)wh_p, n8);

    // 4) output projection: out[32768,1152] = oh @ w_o^T  (fp16 mma, fp32 acc)
    gemm_f16<<<dim3(DMODEL / 128, MTOK / 256), 256, GEMM_SMEM>>>(
        oh_p, wh_p, out, DMODEL, DMODEL);
}

// round 6
// speedup vs baseline: 6.6337x; 1.1358x over previous
#include <cuda_runtime.h>
#include <cuda_fp16.h>
#include <math.h>
#include <stdint.h>

// ---------------- problem constants (fixed by setup_inputs) ----------------
#define BFRAMES   128          // B*T = 8*16
#define SEQ       256          // H*W = 16*16
#define DMODEL    1152
#define NHEADS    12
#define NGROUPS   4
#define HEADDIM   96
#define QKV_N     1920         // 12*96 + 2*4*96
#define MTOK      32768        // BFRAMES*SEQ
#define SM_SCALE  0.1020620726159658f   // 96^-0.5

// ---------------- scratch (device globals; no allocation allowed) ----------
__device__ __half g_xh[(size_t)MTOK * DMODEL];      // fp16 x
__device__ __half g_wh[(size_t)QKV_N * DMODEL];     // fp16 weights (reused)
__device__ __half g_qkvh[(size_t)MTOK * QKV_N];     // fp16 qkv
__device__ __half g_qh[(size_t)BFRAMES * NHEADS * SEQ * HEADDIM];
__device__ __half g_kh[(size_t)BFRAMES * NGROUPS * SEQ * HEADDIM];
__device__ __half g_vh[(size_t)BFRAMES * NGROUPS * SEQ * HEADDIM];
__device__ __half g_oh[(size_t)MTOK * DMODEL];      // fp16 attention output

// ============================================================================
// helpers
// ============================================================================
__device__ __forceinline__ uint32_t smem_u32(const void* p) {
    uint32_t a;
    asm("{ .reg .u64 t; cvta.to.shared.u64 t, %1; cvt.u32.u64 %0, t; }"
        : "=r"(a) : "l"(p));
    return a;
}

__device__ __forceinline__ void cp_async16(uint32_t saddr, const void* gptr) {
    asm volatile("cp.async.cg.shared.global [%0], [%1], 16;" :: "r"(saddr), "l"(gptr));
}

__device__ __forceinline__ void mma_f16(float c[4], const uint32_t a[4],
                                        const uint32_t b[2]) {
    asm volatile(
        "mma.sync.aligned.m16n8k16.row.col.f32.f16.f16.f32 "
        "{%0,%1,%2,%3}, {%4,%5,%6,%7}, {%8,%9}, {%0,%1,%2,%3};"
        : "+f"(c[0]), "+f"(c[1]), "+f"(c[2]), "+f"(c[3])
        : "r"(a[0]), "r"(a[1]), "r"(a[2]), "r"(a[3]), "r"(b[0]), "r"(b[1]));
}

__device__ __forceinline__ void ldsm4(uint32_t r[4], uint32_t addr) {
    asm volatile("ldmatrix.sync.aligned.m8n8.x4.shared.b16 {%0,%1,%2,%3}, [%4];"
                 : "=r"(r[0]), "=r"(r[1]), "=r"(r[2]), "=r"(r[3]) : "r"(addr));
}

__device__ __forceinline__ void ldsm4t(uint32_t r[4], uint32_t addr) {
    asm volatile("ldmatrix.sync.aligned.m8n8.x4.trans.shared.b16 {%0,%1,%2,%3}, [%4];"
                 : "=r"(r[0]), "=r"(r[1]), "=r"(r[2]), "=r"(r[3]) : "r"(addr));
}

// ============================================================================
// fp16 mma.sync GEMM (NT): C[M,N] = A[M,K] * B[N,K]^T, fp32 accumulate.
// CTA 256x128, BK=32, 4-stage cp.async, 8 warps (64x64), ldmatrix loads.
// Output type templated: float (fp32 store) or __half (half2 store).
// ============================================================================
#define HSTR      40
#define STAGE_H   ((256 + 128) * HSTR)       // 15360 halves
#define NSTAGE    4
#define GEMM_SMEM (NSTAGE * STAGE_H * 2)     // 122880 bytes

template <typename OT>
__global__ __launch_bounds__(256, 1)
void gemm_f16(const __half* __restrict__ A, const __half* __restrict__ B,
              OT* __restrict__ C, int ldC, int K)
{
    extern __shared__ __half smh[];
    const int tid    = threadIdx.x;
    const int lane   = tid & 31;
    const int wid    = tid >> 5;
    const int warp_m = wid & 3;
    const int warp_n = wid >> 2;
    const int m0 = blockIdx.y * 256;
    const int n0 = blockIdx.x * 128;
    const int ITERS = K >> 5;

    const __half* Ag = A + (size_t)m0 * K;
    const __half* Bg = B + (size_t)n0 * K;
    const uint32_t sbase = smem_u32(smh);

    auto load_stage = [&](int chunk, int st) {
        uint32_t abase = sbase + st * (STAGE_H * 2);
        uint32_t bbase = abase + 256 * (HSTR * 2);
        const __half* Ac = Ag + chunk * 32;
        const __half* Bc = Bg + chunk * 32;
#pragma unroll
        for (int j = 0; j < 4; j++) {
            int idx = tid + j * 256;
            int row = idx >> 2, c = idx & 3;
            cp_async16(abase + row * (HSTR * 2) + c * 16,
                       Ac + (size_t)row * K + c * 8);
        }
#pragma unroll
        for (int j = 0; j < 2; j++) {
            int idx = tid + j * 256;
            int row = idx >> 2, c = idx & 3;
            cp_async16(bbase + row * (HSTR * 2) + c * 16,
                       Bc + (size_t)row * K + c * 8);
        }
    };

    float acc[4][8][4];
#pragma unroll
    for (int mt = 0; mt < 4; mt++)
#pragma unroll
        for (int nt = 0; nt < 8; nt++)
#pragma unroll
            for (int r = 0; r < 4; r++) acc[mt][nt][r] = 0.f;

    const int arow = warp_m * 64 + (lane & 15);
    const int acol = (lane >> 4) * 8;
    const int brow = warp_n * 64 + (lane & 7) + (lane >> 4) * 8;
    const int bcol = ((lane >> 3) & 1) * 8;

    load_stage(0, 0);
    asm volatile("cp.async.commit_group;");
    if (ITERS > 1) load_stage(1, 1);
    asm volatile("cp.async.commit_group;");
    if (ITERS > 2) load_stage(2, 2);
    asm volatile("cp.async.commit_group;");

    for (int i = 0; i < ITERS; i++) {
        const int st = i & 3;
        asm volatile("cp.async.wait_group 2;");
        __syncthreads();

        if (i + 3 < ITERS) load_stage(i + 3, (i + 3) & 3);
        asm volatile("cp.async.commit_group;");

        uint32_t abase = sbase + st * (STAGE_H * 2);
        uint32_t bbase = abase + 256 * (HSTR * 2);

#pragma unroll
        for (int kstep = 0; kstep < 2; kstep++) {
            uint32_t af[4][4];
#pragma unroll
            for (int mt = 0; mt < 4; mt++)
                ldsm4(af[mt], abase + ((arow + mt * 16) * HSTR
                                       + kstep * 16 + acol) * 2);
            uint32_t bf[8][2];
#pragma unroll
            for (int ntp = 0; ntp < 4; ntp++) {
                uint32_t r[4];
                ldsm4(r, bbase + ((brow + ntp * 16) * HSTR
                                  + kstep * 16 + bcol) * 2);
                bf[2 * ntp][0] = r[0]; bf[2 * ntp][1] = r[1];
                bf[2 * ntp + 1][0] = r[2]; bf[2 * ntp + 1][1] = r[3];
            }
#pragma unroll
            for (int mt = 0; mt < 4; mt++)
#pragma unroll
                for (int nt = 0; nt < 8; nt++)
                    mma_f16(acc[mt][nt], af[mt], bf[nt]);
        }
        __syncthreads();
    }

#pragma unroll
    for (int mt = 0; mt < 4; mt++) {
        int row0 = m0 + warp_m * 64 + mt * 16 + (lane >> 2);
#pragma unroll
        for (int nt = 0; nt < 8; nt++) {
            int col = n0 + warp_n * 64 + nt * 8 + (lane & 3) * 2;
            if constexpr (sizeof(OT) == 4) {
                *(float2*)((float*)C + (size_t)row0 * ldC + col) =
                    make_float2(acc[mt][nt][0], acc[mt][nt][1]);
                *(float2*)((float*)C + (size_t)(row0 + 8) * ldC + col) =
                    make_float2(acc[mt][nt][2], acc[mt][nt][3]);
            } else {
                *(__half2*)((__half*)C + (size_t)row0 * ldC + col) =
                    __float22half2_rn(make_float2(acc[mt][nt][0], acc[mt][nt][1]));
                *(__half2*)((__half*)C + (size_t)(row0 + 8) * ldC + col) =
                    __float22half2_rn(make_float2(acc[mt][nt][2], acc[mt][nt][3]));
            }
        }
    }
}

// ============================================================================
// convert fp32 -> fp16 (RN), 8 elems per thread
// ============================================================================
__global__ __launch_bounds__(256) void f32_to_f16_kernel(
    const float4* __restrict__ in, uint4* __restrict__ out, int n8)
{
    int i = blockIdx.x * blockDim.x + threadIdx.x;
    if (i >= n8) return;
    float4 a = in[2 * i], b = in[2 * i + 1];
    __half2 h0 = __float22half2_rn(make_float2(a.x, a.y));
    __half2 h1 = __float22half2_rn(make_float2(a.z, a.w));
    __half2 h2 = __float22half2_rn(make_float2(b.x, b.y));
    __half2 h3 = __float22half2_rn(make_float2(b.z, b.w));
    uint4 o;
    o.x = *(uint32_t*)&h0; o.y = *(uint32_t*)&h1;
    o.z = *(uint32_t*)&h2; o.w = *(uint32_t*)&h3;
    out[i] = o;
}

// ============================================================================
// norm + RoPE + layout transpose; fp16 in, fp16 out (math in fp32)
// ============================================================================
__global__ __launch_bounds__(256) void normrope_kernel(const __half* __restrict__ qkv)
{
    const int NQv = MTOK * NHEADS;
    const int NKv = MTOK * NGROUPS;
    int wid  = (blockIdx.x * blockDim.x + threadIdx.x) >> 5;
    int lane = threadIdx.x & 31;
    if (wid >= NQv + 2 * NKv) return;

    const __half* src;
    __half* dst;
    int t;
    bool do_norm_rope = true;

    if (wid < NQv) {
        t = wid / NHEADS; int h = wid % NHEADS;
        src = qkv + (size_t)t * QKV_N + h * HEADDIM;
        int bf = t >> 8, s = t & 255;
        dst = g_qh + ((size_t)(bf * NHEADS + h) * SEQ + s) * HEADDIM;
    } else if (wid < NQv + NKv) {
        int v = wid - NQv; t = v / NGROUPS; int g = v % NGROUPS;
        src = qkv + (size_t)t * QKV_N + DMODEL + g * HEADDIM;
        int bf = t >> 8, s = t & 255;
        dst = g_kh + ((size_t)(bf * NGROUPS + g) * SEQ + s) * HEADDIM;
    } else {
        int v = wid - NQv - NKv; t = v / NGROUPS; int g = v % NGROUPS;
        src = qkv + (size_t)t * QKV_N + DMODEL + NGROUPS * HEADDIM + g * HEADDIM;
        int bf = t >> 8, s = t & 255;
        dst = g_vh + ((size_t)(bf * NGROUPS + g) * SEQ + s) * HEADDIM;
        do_norm_rope = false;
    }

    float x0 = __half2float(src[lane]);
    float x1 = __half2float(src[lane + 32]);
    float x2 = __half2float(src[lane + 64]);

    if (do_norm_rope) {
        float ss = fmaf(x0, x0, fmaf(x1, x1, x2 * x2));
#pragma unroll
        for (int o = 16; o; o >>= 1) ss += __shfl_xor_sync(0xffffffffu, ss, o);
        float inv = 1.0f / fmaxf(sqrtf(ss), 1e-10f);
        x0 *= inv; x1 *= inv; x2 *= inv;

        int s = t & 255;
        float pos = (float)((s >> 4) + (s & 15));
        int i = lane & 15;
        float a = __shfl_sync(0xffffffffu, x0, 2 * i);
        float b = __shfl_sync(0xffffffffu, x0, 2 * i + 1);
        float invf = exp2f(-(float)i * 0.8304820237218406f);
        float ang = pos * invf;
        float sn, cs;
        sincosf(ang, &sn, &cs);
        x0 = (lane < 16) ? fmaf(a, cs, -b * sn) : fmaf(a, sn, b * cs);
    }

    dst[lane]      = __float2half_rn(x0);
    dst[lane + 32] = __float2half_rn(x1);
    dst[lane + 64] = __float2half_rn(x2);
}

// ============================================================================
// Flash attention, fp16 mma.sync m16n8k16, fp32 accum/softmax.
// CTA = (q-half of 128 rows, head, bf); 8 warps x 16 q-rows.
// K/V/P in static smem; strides 104/104/72 halves (conflict-free LDSM).
// ============================================================================
#define KS 104
#define VS 104
#define PS 72

__global__ __launch_bounds__(256, 1) void attn_kernel()
{
    __shared__ __half sK[64 * KS];
    __shared__ __half sV[64 * VS];
    __shared__ __half sP[128 * PS];

    const int tid  = threadIdx.x;
    const int lane = tid & 31;
    const int wid  = tid >> 5;
    const int half = blockIdx.x;
    const int h    = blockIdx.y;
    const int bf   = blockIdx.z;
    const int g    = h / 3;

    const __half* Qg = g_qh + ((size_t)(bf * NHEADS + h) * SEQ + half * 128 + wid * 16) * HEADDIM;
    const __half* Kg = g_kh + (size_t)(bf * NGROUPS + g) * SEQ * HEADDIM;
    const __half* Vg = g_vh + (size_t)(bf * NGROUPS + g) * SEQ * HEADDIM;

    // Q fragments: 6 k16-steps
    uint32_t qf[6][4];
    {
        const __half* q0 = Qg + (lane >> 2) * HEADDIM;
        const __half* q1 = Qg + ((lane >> 2) + 8) * HEADDIM;
        int cc = 2 * (lane & 3);
#pragma unroll
        for (int j = 0; j < 6; j++) {
            qf[j][0] = *(const uint32_t*)(q0 + j * 16 + cc);
            qf[j][1] = *(const uint32_t*)(q1 + j * 16 + cc);
            qf[j][2] = *(const uint32_t*)(q0 + j * 16 + 8 + cc);
            qf[j][3] = *(const uint32_t*)(q1 + j * 16 + 8 + cc);
        }
    }

    const uint32_t sKb = smem_u32(sK);
    const uint32_t sVb = smem_u32(sV);
    const uint32_t sPw = smem_u32(sP) + wid * 16 * PS * 2;
    __half* Pw = sP + wid * 16 * PS;

    const int idx  = lane >> 3;   // ldmatrix matrix index
    const int lrow = lane & 7;

    float m_a = -INFINITY, m_b = -INFINITY;
    float l_a = 0.f, l_b = 0.f;
    float oacc[12][4];
#pragma unroll
    for (int nt = 0; nt < 12; nt++)
#pragma unroll
        for (int r = 0; r < 4; r++) oacc[nt][r] = 0.f;

    for (int kt = 0; kt < 4; kt++) {
        __syncthreads();
        {
            const __half* Kc = Kg + (size_t)kt * 64 * HEADDIM;
            const __half* Vc = Vg + (size_t)kt * 64 * HEADDIM;
#pragma unroll
            for (int it = 0; it < 3; it++) {
                int i = tid + it * 256;          // 768 chunks of 16B
                int r = i / 12, c = (i % 12) * 8;
                *(uint4*)(sK + r * KS + c) = *(const uint4*)(Kc + r * HEADDIM + c);
                *(uint4*)(sV + r * VS + c) = *(const uint4*)(Vc + r * HEADDIM + c);
            }
        }
        __syncthreads();

        // ---- S = Q K^T ----
        float sacc[8][4];
#pragma unroll
        for (int nt = 0; nt < 8; nt++)
#pragma unroll
            for (int r = 0; r < 4; r++) sacc[nt][r] = 0.f;

#pragma unroll
        for (int j = 0; j < 6; j++) {
#pragma unroll
            for (int nt2 = 0; nt2 < 4; nt2++) {
                uint32_t r[4];
                // M0/M1: keys 0..7, dims j16+{0,8}; M2/M3: keys 8..15
                ldsm4(r, sKb + ((nt2 * 16 + (idx >> 1) * 8 + lrow) * KS
                                + j * 16 + (idx & 1) * 8) * 2);
                uint32_t b0[2] = {r[0], r[1]};
                uint32_t b1[2] = {r[2], r[3]};
                mma_f16(sacc[2 * nt2], qf[j], b0);
                mma_f16(sacc[2 * nt2 + 1], qf[j], b1);
            }
        }

        // ---- online softmax ----
        float tmax_a = -INFINITY, tmax_b = -INFINITY;
#pragma unroll
        for (int nt = 0; nt < 8; nt++) {
#pragma unroll
            for (int r = 0; r < 4; r++) sacc[nt][r] *= SM_SCALE;
            tmax_a = fmaxf(tmax_a, fmaxf(sacc[nt][0], sacc[nt][1]));
            tmax_b = fmaxf(tmax_b, fmaxf(sacc[nt][2], sacc[nt][3]));
        }
        tmax_a = fmaxf(tmax_a, __shfl_xor_sync(0xffffffffu, tmax_a, 1));
        tmax_a = fmaxf(tmax_a, __shfl_xor_sync(0xffffffffu, tmax_a, 2));
        tmax_b = fmaxf(tmax_b, __shfl_xor_sync(0xffffffffu, tmax_b, 1));
        tmax_b = fmaxf(tmax_b, __shfl_xor_sync(0xffffffffu, tmax_b, 2));

        float mn_a = fmaxf(m_a, tmax_a);
        float mn_b = fmaxf(m_b, tmax_b);
        float al_a = __expf(m_a - mn_a);
        float al_b = __expf(m_b - mn_b);
        m_a = mn_a; m_b = mn_b;

        __syncwarp();   // previous chunk's P reads done before overwrite

        float sum_a = 0.f, sum_b = 0.f;
        {
            int r0 = (lane >> 2);
            int cc = 2 * (lane & 3);
#pragma unroll
            for (int nt = 0; nt < 8; nt++) {
                float p0 = __expf(sacc[nt][0] - mn_a);
                float p1 = __expf(sacc[nt][1] - mn_a);
                float p2 = __expf(sacc[nt][2] - mn_b);
                float p3 = __expf(sacc[nt][3] - mn_b);
                sum_a += p0 + p1;
                sum_b += p2 + p3;
                int col = nt * 8 + cc;
                *(__half2*)(Pw + r0 * PS + col) =
                    __float22half2_rn(make_float2(p0, p1));
                *(__half2*)(Pw + (r0 + 8) * PS + col) =
                    __float22half2_rn(make_float2(p2, p3));
            }
        }
        sum_a += __shfl_xor_sync(0xffffffffu, sum_a, 1);
        sum_a += __shfl_xor_sync(0xffffffffu, sum_a, 2);
        sum_b += __shfl_xor_sync(0xffffffffu, sum_b, 1);
        sum_b += __shfl_xor_sync(0xffffffffu, sum_b, 2);
        l_a = l_a * al_a + sum_a;
        l_b = l_b * al_b + sum_b;

#pragma unroll
        for (int nt = 0; nt < 12; nt++) {
            oacc[nt][0] *= al_a; oacc[nt][1] *= al_a;
            oacc[nt][2] *= al_b; oacc[nt][3] *= al_b;
        }

        __syncwarp();   // P writes visible within warp

        // ---- O += P V ----
#pragma unroll
        for (int jj = 0; jj < 4; jj++) {
            uint32_t af[4];
            // A from P: M0 rows0-7 k0-7, M1 rows8-15 k0-7, M2 rows0-7 k8-15, M3 rows8-15 k8-15
            ldsm4(af, sPw + (((idx & 1) * 8 + lrow) * PS
                             + jj * 16 + (idx >> 1) * 8) * 2);
#pragma unroll
            for (int dt2 = 0; dt2 < 6; dt2++) {
                uint32_t r[4];
                // B from V (trans): M0 keys jj16+0..7 dims dt2*16+0..7, M1 keys+8,
                // M2 dims+8, M3 keys+8 dims+8
                ldsm4t(r, sVb + ((jj * 16 + (idx & 1) * 8 + lrow) * VS
                                 + dt2 * 16 + (idx >> 1) * 8) * 2);
                uint32_t b0[2] = {r[0], r[1]};
                uint32_t b1[2] = {r[2], r[3]};
                mma_f16(oacc[2 * dt2], af, b0);
                mma_f16(oacc[2 * dt2 + 1], af, b1);
            }
        }
    }

    // ---- epilogue: normalize, convert to fp16, store to g_oh ----
    float invla = 1.0f / l_a;
    float invlb = 1.0f / l_b;
    int row0 = half * 128 + wid * 16 + (lane >> 2);
    __half* o0 = g_oh + (size_t)(bf * SEQ + row0) * DMODEL + h * HEADDIM;
    __half* o1 = g_oh + (size_t)(bf * SEQ + row0 + 8) * DMODEL + h * HEADDIM;
#pragma unroll
    for (int nt = 0; nt < 12; nt++) {
        int col = nt * 8 + 2 * (lane & 3);
        *(__half2*)(o0 + col) = __float22half2_rn(
            make_float2(oacc[nt][0] * invla, oacc[nt][1] * invla));
        *(__half2*)(o1 + col) = __float22half2_rn(
            make_float2(oacc[nt][2] * invlb, oacc[nt][3] * invlb));
    }
}

// ============================================================================
// launch
// ============================================================================
extern "C" void kernel_launch(void* const* d_in, const int* in_sizes, int n_in,
                              void* d_out, int out_size)
{
    const float* x     = (const float*)d_in[0];
    const float* w_qkv = (const float*)d_in[1];
    const float* w_o   = (const float*)d_in[2];
    float* out = (float*)d_out;

    __half *xh_p, *wh_p, *qkvh_p, *oh_p;
    cudaGetSymbolAddress((void**)&xh_p, g_xh);
    cudaGetSymbolAddress((void**)&wh_p, g_wh);
    cudaGetSymbolAddress((void**)&qkvh_p, g_qkvh);
    cudaGetSymbolAddress((void**)&oh_p, g_oh);

    cudaFuncSetAttribute(gemm_f16<__half>,
                         cudaFuncAttributeMaxDynamicSharedMemorySize, GEMM_SMEM);
    cudaFuncSetAttribute(gemm_f16<float>,
                         cudaFuncAttributeMaxDynamicSharedMemorySize, GEMM_SMEM);

    int n8;

    // convert x -> fp16, w_qkv -> fp16
    n8 = MTOK * DMODEL / 8;
    f32_to_f16_kernel<<<(n8 + 255) / 256, 256>>>((const float4*)x, (uint4*)xh_p, n8);
    n8 = QKV_N * DMODEL / 8;
    f32_to_f16_kernel<<<(n8 + 255) / 256, 256>>>((const float4*)w_qkv, (uint4*)wh_p, n8);

    // 1) QKV projection: qkvh[32768,1920] = xh @ w_qkv^T  (fp16 out)
    gemm_f16<__half><<<dim3(QKV_N / 128, MTOK / 256), 256, GEMM_SMEM>>>(
        xh_p, wh_p, qkvh_p, QKV_N, DMODEL);

    // 2) qk-norm + spatial RoPE + transpose (fp16 q/k/v)
    {
        int total_warps = MTOK * NHEADS + 2 * MTOK * NGROUPS;
        normrope_kernel<<<total_warps / 8, 256>>>(qkvh_p);
    }

    // 3) flash attention (fp16 mma; writes fp16 g_oh)
    attn_kernel<<<dim3(2, NHEADS, BFRAMES), 256>>>();

    // convert w_o -> fp16
    n8 = DMODEL * DMODEL / 8;
    f32_to_f16_kernel<<<(n8 + 255) / 256, 256>>>((const float4*)w_o, (uint4*)wh_p, n8);

    // 4) output projection: out[32768,1152] = oh @ w_o^T  (fp32 out)
    gemm_f16<float><<<dim3(DMODEL / 128, MTOK / 256), 256, GEMM_SMEM>>>(
        oh_p, wh_p, out, DMODEL, DMODEL);
}

// round 7
// speedup vs baseline: 7.4445x; 1.1222x over previous
#include <cuda_runtime.h>
#include <cuda_fp16.h>
#include <math.h>
#include <stdint.h>

// ---------------- problem constants (fixed by setup_inputs) ----------------
#define BFRAMES   128          // B*T = 8*16
#define SEQ       256          // H*W = 16*16
#define DMODEL    1152
#define NHEADS    12
#define NGROUPS   4
#define HEADDIM   96
#define QKV_N     1920         // 12*96 + 2*4*96
#define MTOK      32768        // BFRAMES*SEQ
#define SM_SCALE  0.1020620726159658f   // 96^-0.5

// ---------------- scratch (device globals; no allocation allowed) ----------
__device__ __half g_xh[(size_t)MTOK * DMODEL];      // fp16 x
__device__ __half g_wh[(size_t)QKV_N * DMODEL];     // fp16 weights (reused)
__device__ __half g_qkvh[(size_t)MTOK * QKV_N];     // fp16 qkv
__device__ __half g_qh[(size_t)BFRAMES * NHEADS * SEQ * HEADDIM];
__device__ __half g_kh[(size_t)BFRAMES * NGROUPS * SEQ * HEADDIM];
__device__ __half g_vh[(size_t)BFRAMES * NGROUPS * SEQ * HEADDIM];
__device__ __half g_oh[(size_t)MTOK * DMODEL];      // fp16 attention output

// ============================================================================
// helpers
// ============================================================================
__device__ __forceinline__ uint32_t smem_u32(const void* p) {
    uint32_t a;
    asm("{ .reg .u64 t; cvta.to.shared.u64 t, %1; cvt.u32.u64 %0, t; }"
        : "=r"(a) : "l"(p));
    return a;
}

__device__ __forceinline__ void cp_async16(uint32_t saddr, const void* gptr) {
    asm volatile("cp.async.cg.shared.global [%0], [%1], 16;" :: "r"(saddr), "l"(gptr));
}

__device__ __forceinline__ void mma_f16(float c[4], const uint32_t a[4],
                                        const uint32_t b[2]) {
    asm volatile(
        "mma.sync.aligned.m16n8k16.row.col.f32.f16.f16.f32 "
        "{%0,%1,%2,%3}, {%4,%5,%6,%7}, {%8,%9}, {%0,%1,%2,%3};"
        : "+f"(c[0]), "+f"(c[1]), "+f"(c[2]), "+f"(c[3])
        : "r"(a[0]), "r"(a[1]), "r"(a[2]), "r"(a[3]), "r"(b[0]), "r"(b[1]));
}

__device__ __forceinline__ void ldsm4(uint32_t r[4], uint32_t addr) {
    asm volatile("ldmatrix.sync.aligned.m8n8.x4.shared.b16 {%0,%1,%2,%3}, [%4];"
                 : "=r"(r[0]), "=r"(r[1]), "=r"(r[2]), "=r"(r[3]) : "r"(addr));
}

__device__ __forceinline__ void ldsm4t(uint32_t r[4], uint32_t addr) {
    asm volatile("ldmatrix.sync.aligned.m8n8.x4.trans.shared.b16 {%0,%1,%2,%3}, [%4];"
                 : "=r"(r[0]), "=r"(r[1]), "=r"(r[2]), "=r"(r[3]) : "r"(addr));
}

// ============================================================================
// fp16 mma.sync GEMM (NT): C[M,N] = A[M,K] * B[N,K]^T, fp32 accumulate.
// CTA 256x128, BK=64, 3-stage cp.async, single __syncthreads per iter,
// 8 warps (warp tile 64x64), ldmatrix loads.
// Smem rows padded to 72 halves (144B) -> all LDSM phases conflict-free.
// ============================================================================
#define HSTR      72
#define STAGE_H   ((256 + 128) * HSTR)       // 27648 halves
#define NSTAGE    3
#define GEMM_SMEM (NSTAGE * STAGE_H * 2)     // 165888 bytes

template <typename OT>
__global__ __launch_bounds__(256, 1)
void gemm_f16(const __half* __restrict__ A, const __half* __restrict__ B,
              OT* __restrict__ C, int ldC, int K)
{
    extern __shared__ __half smh[];
    const int tid    = threadIdx.x;
    const int lane   = tid & 31;
    const int wid    = tid >> 5;
    const int warp_m = wid & 3;
    const int warp_n = wid >> 2;
    const int m0 = blockIdx.y * 256;
    const int n0 = blockIdx.x * 128;
    const int ITERS = K >> 6;            // BK = 64

    const __half* Ag = A + (size_t)m0 * K;
    const __half* Bg = B + (size_t)n0 * K;
    const uint32_t sbase = smem_u32(smh);

    auto load_stage = [&](int chunk, int st) {
        uint32_t abase = sbase + st * (STAGE_H * 2);
        uint32_t bbase = abase + 256 * (HSTR * 2);
        const __half* Ac = Ag + chunk * 64;
        const __half* Bc = Bg + chunk * 64;
#pragma unroll
        for (int j = 0; j < 8; j++) {            // A: 256 rows x 8 chunks of 16B
            int idx = tid + j * 256;
            int row = idx >> 3, c = idx & 7;
            cp_async16(abase + row * (HSTR * 2) + c * 16,
                       Ac + (size_t)row * K + c * 8);
        }
#pragma unroll
        for (int j = 0; j < 4; j++) {            // B: 128 rows x 8 chunks of 16B
            int idx = tid + j * 256;
            int row = idx >> 3, c = idx & 7;
            cp_async16(bbase + row * (HSTR * 2) + c * 16,
                       Bc + (size_t)row * K + c * 8);
        }
    };

    float acc[4][8][4];
#pragma unroll
    for (int mt = 0; mt < 4; mt++)
#pragma unroll
        for (int nt = 0; nt < 8; nt++)
#pragma unroll
            for (int r = 0; r < 4; r++) acc[mt][nt][r] = 0.f;

    // ldmatrix per-thread row/col offsets (halves), within a stage
    const int arow = warp_m * 64 + (lane & 15);          // + mt*16
    const int acol = (lane >> 4) * 8;                    // + kstep*16
    const int brow = warp_n * 64 + (lane & 7) + (lane >> 4) * 8;  // + ntp*16
    const int bcol = ((lane >> 3) & 1) * 8;              // + kstep*16

    load_stage(0, 0);
    asm volatile("cp.async.commit_group;");
    if (ITERS > 1) load_stage(1, 1);
    asm volatile("cp.async.commit_group;");

    for (int i = 0; i < ITERS; i++) {
        // stage i%3 is ready once <=1 groups remain outstanding
        asm volatile("cp.async.wait_group 1;");
        __syncthreads();   // publishes stage i%3; proves compute(i-1) done on (i+2)%3

        if (i + 2 < ITERS) load_stage(i + 2, (i + 2) % 3);
        asm volatile("cp.async.commit_group;");

        const int st = i % 3;
        uint32_t abase = sbase + st * (STAGE_H * 2);
        uint32_t bbase = abase + 256 * (HSTR * 2);

#pragma unroll
        for (int kstep = 0; kstep < 4; kstep++) {
            uint32_t af[4][4];
#pragma unroll
            for (int mt = 0; mt < 4; mt++)
                ldsm4(af[mt], abase + ((arow + mt * 16) * HSTR
                                       + kstep * 16 + acol) * 2);
            uint32_t bf[8][2];
#pragma unroll
            for (int ntp = 0; ntp < 4; ntp++) {
                uint32_t r[4];
                ldsm4(r, bbase + ((brow + ntp * 16) * HSTR
                                  + kstep * 16 + bcol) * 2);
                bf[2 * ntp][0] = r[0]; bf[2 * ntp][1] = r[1];
                bf[2 * ntp + 1][0] = r[2]; bf[2 * ntp + 1][1] = r[3];
            }
#pragma unroll
            for (int mt = 0; mt < 4; mt++)
#pragma unroll
                for (int nt = 0; nt < 8; nt++)
                    mma_f16(acc[mt][nt], af[mt], bf[nt]);
        }
        // no trailing barrier: next iter's top barrier provides the hazard fence
    }

#pragma unroll
    for (int mt = 0; mt < 4; mt++) {
        int row0 = m0 + warp_m * 64 + mt * 16 + (lane >> 2);
#pragma unroll
        for (int nt = 0; nt < 8; nt++) {
            int col = n0 + warp_n * 64 + nt * 8 + (lane & 3) * 2;
            if constexpr (sizeof(OT) == 4) {
                *(float2*)((float*)C + (size_t)row0 * ldC + col) =
                    make_float2(acc[mt][nt][0], acc[mt][nt][1]);
                *(float2*)((float*)C + (size_t)(row0 + 8) * ldC + col) =
                    make_float2(acc[mt][nt][2], acc[mt][nt][3]);
            } else {
                *(__half2*)((__half*)C + (size_t)row0 * ldC + col) =
                    __float22half2_rn(make_float2(acc[mt][nt][0], acc[mt][nt][1]));
                *(__half2*)((__half*)C + (size_t)(row0 + 8) * ldC + col) =
                    __float22half2_rn(make_float2(acc[mt][nt][2], acc[mt][nt][3]));
            }
        }
    }
}

// ============================================================================
// convert fp32 -> fp16 (RN), 8 elems per thread
// ============================================================================
__global__ __launch_bounds__(256) void f32_to_f16_kernel(
    const float4* __restrict__ in, uint4* __restrict__ out, int n8)
{
    int i = blockIdx.x * blockDim.x + threadIdx.x;
    if (i >= n8) return;
    float4 a = in[2 * i], b = in[2 * i + 1];
    __half2 h0 = __float22half2_rn(make_float2(a.x, a.y));
    __half2 h1 = __float22half2_rn(make_float2(a.z, a.w));
    __half2 h2 = __float22half2_rn(make_float2(b.x, b.y));
    __half2 h3 = __float22half2_rn(make_float2(b.z, b.w));
    uint4 o;
    o.x = *(uint32_t*)&h0; o.y = *(uint32_t*)&h1;
    o.z = *(uint32_t*)&h2; o.w = *(uint32_t*)&h3;
    out[i] = o;
}

// ============================================================================
// norm + RoPE + layout transpose; fp16 in, fp16 out (math in fp32)
// ============================================================================
__global__ __launch_bounds__(256) void normrope_kernel(const __half* __restrict__ qkv)
{
    const int NQv = MTOK * NHEADS;
    const int NKv = MTOK * NGROUPS;
    int wid  = (blockIdx.x * blockDim.x + threadIdx.x) >> 5;
    int lane = threadIdx.x & 31;
    if (wid >= NQv + 2 * NKv) return;

    const __half* src;
    __half* dst;
    int t;
    bool do_norm_rope = true;

    if (wid < NQv) {
        t = wid / NHEADS; int h = wid % NHEADS;
        src = qkv + (size_t)t * QKV_N + h * HEADDIM;
        int bf = t >> 8, s = t & 255;
        dst = g_qh + ((size_t)(bf * NHEADS + h) * SEQ + s) * HEADDIM;
    } else if (wid < NQv + NKv) {
        int v = wid - NQv; t = v / NGROUPS; int g = v % NGROUPS;
        src = qkv + (size_t)t * QKV_N + DMODEL + g * HEADDIM;
        int bf = t >> 8, s = t & 255;
        dst = g_kh + ((size_t)(bf * NGROUPS + g) * SEQ + s) * HEADDIM;
    } else {
        int v = wid - NQv - NKv; t = v / NGROUPS; int g = v % NGROUPS;
        src = qkv + (size_t)t * QKV_N + DMODEL + NGROUPS * HEADDIM + g * HEADDIM;
        int bf = t >> 8, s = t & 255;
        dst = g_vh + ((size_t)(bf * NGROUPS + g) * SEQ + s) * HEADDIM;
        do_norm_rope = false;
    }

    float x0 = __half2float(src[lane]);
    float x1 = __half2float(src[lane + 32]);
    float x2 = __half2float(src[lane + 64]);

    if (do_norm_rope) {
        float ss = fmaf(x0, x0, fmaf(x1, x1, x2 * x2));
#pragma unroll
        for (int o = 16; o; o >>= 1) ss += __shfl_xor_sync(0xffffffffu, ss, o);
        float inv = 1.0f / fmaxf(sqrtf(ss), 1e-10f);
        x0 *= inv; x1 *= inv; x2 *= inv;

        int s = t & 255;
        float pos = (float)((s >> 4) + (s & 15));
        int i = lane & 15;
        float a = __shfl_sync(0xffffffffu, x0, 2 * i);
        float b = __shfl_sync(0xffffffffu, x0, 2 * i + 1);
        float invf = exp2f(-(float)i * 0.8304820237218406f);
        float ang = pos * invf;
        float sn, cs;
        sincosf(ang, &sn, &cs);
        x0 = (lane < 16) ? fmaf(a, cs, -b * sn) : fmaf(a, sn, b * cs);
    }

    dst[lane]      = __float2half_rn(x0);
    dst[lane + 32] = __float2half_rn(x1);
    dst[lane + 64] = __float2half_rn(x2);
}

// ============================================================================
// Flash attention, fp16 mma.sync m16n8k16, fp32 accum/softmax (R6-proven)
// ============================================================================
#define KS 104
#define VS 104
#define PS 72

__global__ __launch_bounds__(256, 1) void attn_kernel()
{
    __shared__ __half sK[64 * KS];
    __shared__ __half sV[64 * VS];
    __shared__ __half sP[128 * PS];

    const int tid  = threadIdx.x;
    const int lane = tid & 31;
    const int wid  = tid >> 5;
    const int half = blockIdx.x;
    const int h    = blockIdx.y;
    const int bf   = blockIdx.z;
    const int g    = h / 3;

    const __half* Qg = g_qh + ((size_t)(bf * NHEADS + h) * SEQ + half * 128 + wid * 16) * HEADDIM;
    const __half* Kg = g_kh + (size_t)(bf * NGROUPS + g) * SEQ * HEADDIM;
    const __half* Vg = g_vh + (size_t)(bf * NGROUPS + g) * SEQ * HEADDIM;

    uint32_t qf[6][4];
    {
        const __half* q0 = Qg + (lane >> 2) * HEADDIM;
        const __half* q1 = Qg + ((lane >> 2) + 8) * HEADDIM;
        int cc = 2 * (lane & 3);
#pragma unroll
        for (int j = 0; j < 6; j++) {
            qf[j][0] = *(const uint32_t*)(q0 + j * 16 + cc);
            qf[j][1] = *(const uint32_t*)(q1 + j * 16 + cc);
            qf[j][2] = *(const uint32_t*)(q0 + j * 16 + 8 + cc);
            qf[j][3] = *(const uint32_t*)(q1 + j * 16 + 8 + cc);
        }
    }

    const uint32_t sKb = smem_u32(sK);
    const uint32_t sVb = smem_u32(sV);
    const uint32_t sPw = smem_u32(sP) + wid * 16 * PS * 2;
    __half* Pw = sP + wid * 16 * PS;

    const int idx  = lane >> 3;
    const int lrow = lane & 7;

    float m_a = -INFINITY, m_b = -INFINITY;
    float l_a = 0.f, l_b = 0.f;
    float oacc[12][4];
#pragma unroll
    for (int nt = 0; nt < 12; nt++)
#pragma unroll
        for (int r = 0; r < 4; r++) oacc[nt][r] = 0.f;

    for (int kt = 0; kt < 4; kt++) {
        __syncthreads();
        {
            const __half* Kc = Kg + (size_t)kt * 64 * HEADDIM;
            const __half* Vc = Vg + (size_t)kt * 64 * HEADDIM;
#pragma unroll
            for (int it = 0; it < 3; it++) {
                int i = tid + it * 256;
                int r = i / 12, c = (i % 12) * 8;
                *(uint4*)(sK + r * KS + c) = *(const uint4*)(Kc + r * HEADDIM + c);
                *(uint4*)(sV + r * VS + c) = *(const uint4*)(Vc + r * HEADDIM + c);
            }
        }
        __syncthreads();

        float sacc[8][4];
#pragma unroll
        for (int nt = 0; nt < 8; nt++)
#pragma unroll
            for (int r = 0; r < 4; r++) sacc[nt][r] = 0.f;

#pragma unroll
        for (int j = 0; j < 6; j++) {
#pragma unroll
            for (int nt2 = 0; nt2 < 4; nt2++) {
                uint32_t r[4];
                ldsm4(r, sKb + ((nt2 * 16 + (idx >> 1) * 8 + lrow) * KS
                                + j * 16 + (idx & 1) * 8) * 2);
                uint32_t b0[2] = {r[0], r[1]};
                uint32_t b1[2] = {r[2], r[3]};
                mma_f16(sacc[2 * nt2], qf[j], b0);
                mma_f16(sacc[2 * nt2 + 1], qf[j], b1);
            }
        }

        float tmax_a = -INFINITY, tmax_b = -INFINITY;
#pragma unroll
        for (int nt = 0; nt < 8; nt++) {
#pragma unroll
            for (int r = 0; r < 4; r++) sacc[nt][r] *= SM_SCALE;
            tmax_a = fmaxf(tmax_a, fmaxf(sacc[nt][0], sacc[nt][1]));
            tmax_b = fmaxf(tmax_b, fmaxf(sacc[nt][2], sacc[nt][3]));
        }
        tmax_a = fmaxf(tmax_a, __shfl_xor_sync(0xffffffffu, tmax_a, 1));
        tmax_a = fmaxf(tmax_a, __shfl_xor_sync(0xffffffffu, tmax_a, 2));
        tmax_b = fmaxf(tmax_b, __shfl_xor_sync(0xffffffffu, tmax_b, 1));
        tmax_b = fmaxf(tmax_b, __shfl_xor_sync(0xffffffffu, tmax_b, 2));

        float mn_a = fmaxf(m_a, tmax_a);
        float mn_b = fmaxf(m_b, tmax_b);
        float al_a = __expf(m_a - mn_a);
        float al_b = __expf(m_b - mn_b);
        m_a = mn_a; m_b = mn_b;

        __syncwarp();

        float sum_a = 0.f, sum_b = 0.f;
        {
            int r0 = (lane >> 2);
            int cc = 2 * (lane & 3);
#pragma unroll
            for (int nt = 0; nt < 8; nt++) {
                float p0 = __expf(sacc[nt][0] - mn_a);
                float p1 = __expf(sacc[nt][1] - mn_a);
                float p2 = __expf(sacc[nt][2] - mn_b);
                float p3 = __expf(sacc[nt][3] - mn_b);
                sum_a += p0 + p1;
                sum_b += p2 + p3;
                int col = nt * 8 + cc;
                *(__half2*)(Pw + r0 * PS + col) =
                    __float22half2_rn(make_float2(p0, p1));
                *(__half2*)(Pw + (r0 + 8) * PS + col) =
                    __float22half2_rn(make_float2(p2, p3));
            }
        }
        sum_a += __shfl_xor_sync(0xffffffffu, sum_a, 1);
        sum_a += __shfl_xor_sync(0xffffffffu, sum_a, 2);
        sum_b += __shfl_xor_sync(0xffffffffu, sum_b, 1);
        sum_b += __shfl_xor_sync(0xffffffffu, sum_b, 2);
        l_a = l_a * al_a + sum_a;
        l_b = l_b * al_b + sum_b;

#pragma unroll
        for (int nt = 0; nt < 12; nt++) {
            oacc[nt][0] *= al_a; oacc[nt][1] *= al_a;
            oacc[nt][2] *= al_b; oacc[nt][3] *= al_b;
        }

        __syncwarp();

#pragma unroll
        for (int jj = 0; jj < 4; jj++) {
            uint32_t af[4];
            ldsm4(af, sPw + (((idx & 1) * 8 + lrow) * PS
                             + jj * 16 + (idx >> 1) * 8) * 2);
#pragma unroll
            for (int dt2 = 0; dt2 < 6; dt2++) {
                uint32_t r[4];
                ldsm4t(r, sVb + ((jj * 16 + (idx & 1) * 8 + lrow) * VS
                                 + dt2 * 16 + (idx >> 1) * 8) * 2);
                uint32_t b0[2] = {r[0], r[1]};
                uint32_t b1[2] = {r[2], r[3]};
                mma_f16(oacc[2 * dt2], af, b0);
                mma_f16(oacc[2 * dt2 + 1], af, b1);
            }
        }
    }

    float invla = 1.0f / l_a;
    float invlb = 1.0f / l_b;
    int row0 = half * 128 + wid * 16 + (lane >> 2);
    __half* o0 = g_oh + (size_t)(bf * SEQ + row0) * DMODEL + h * HEADDIM;
    __half* o1 = g_oh + (size_t)(bf * SEQ + row0 + 8) * DMODEL + h * HEADDIM;
#pragma unroll
    for (int nt = 0; nt < 12; nt++) {
        int col = nt * 8 + 2 * (lane & 3);
        *(__half2*)(o0 + col) = __float22half2_rn(
            make_float2(oacc[nt][0] * invla, oacc[nt][1] * invla));
        *(__half2*)(o1 + col) = __float22half2_rn(
            make_float2(oacc[nt][2] * invlb, oacc[nt][3] * invlb));
    }
}

// ============================================================================
// launch
// ============================================================================
extern "C" void kernel_launch(void* const* d_in, const int* in_sizes, int n_in,
                              void* d_out, int out_size)
{
    const float* x     = (const float*)d_in[0];
    const float* w_qkv = (const float*)d_in[1];
    const float* w_o   = (const float*)d_in[2];
    float* out = (float*)d_out;

    __half *xh_p, *wh_p, *qkvh_p, *oh_p;
    cudaGetSymbolAddress((void**)&xh_p, g_xh);
    cudaGetSymbolAddress((void**)&wh_p, g_wh);
    cudaGetSymbolAddress((void**)&qkvh_p, g_qkvh);
    cudaGetSymbolAddress((void**)&oh_p, g_oh);

    cudaFuncSetAttribute(gemm_f16<__half>,
                         cudaFuncAttributeMaxDynamicSharedMemorySize, GEMM_SMEM);
    cudaFuncSetAttribute(gemm_f16<float>,
                         cudaFuncAttributeMaxDynamicSharedMemorySize, GEMM_SMEM);

    int n8;

    // convert x -> fp16, w_qkv -> fp16
    n8 = MTOK * DMODEL / 8;
    f32_to_f16_kernel<<<(n8 + 255) / 256, 256>>>((const float4*)x, (uint4*)xh_p, n8);
    n8 = QKV_N * DMODEL / 8;
    f32_to_f16_kernel<<<(n8 + 255) / 256, 256>>>((const float4*)w_qkv, (uint4*)wh_p, n8);

    // 1) QKV projection: qkvh[32768,1920] = xh @ w_qkv^T  (fp16 out)
    gemm_f16<__half><<<dim3(QKV_N / 128, MTOK / 256), 256, GEMM_SMEM>>>(
        xh_p, wh_p, qkvh_p, QKV_N, DMODEL);

    // 2) qk-norm + spatial RoPE + transpose (fp16 q/k/v)
    {
        int total_warps = MTOK * NHEADS + 2 * MTOK * NGROUPS;
        normrope_kernel<<<total_warps / 8, 256>>>(qkvh_p);
    }

    // 3) flash attention (fp16 mma; writes fp16 g_oh)
    attn_kernel<<<dim3(2, NHEADS, BFRAMES), 256>>>();

    // convert w_o -> fp16
    n8 = DMODEL * DMODEL / 8;
    f32_to_f16_kernel<<<(n8 + 255) / 256, 256>>>((const float4*)w_o, (uint4*)wh_p, n8);

    // 4) output projection: out[32768,1152] = oh @ w_o^T  (fp32 out)
    gemm_f16<float><<<dim3(DMODEL / 128, MTOK / 256), 256, GEMM_SMEM>>>(
        oh_p, wh_p, out, DMODEL, DMODEL);
}